// round 13
// baseline (speedup 1.0000x reference)
#include <cuda_runtime.h>
#include <cuda_bf16.h>
#include <math.h>
#include <stdint.h>

// ---------------------------------------------------------------------------
// StandardPartitionAttention  (Swin-style window attention, DEPTH=2)
// R13: tcgen05 tf32 GEMMs guarded by __CUDA_ARCH_FEAT_SM103_ALL (the harness
//      also builds a non-'a' pass that rejects tcgen05); fp32 fallback there.
//      Fixed R12 stage loader (full 128B/row: 8x16B per operand per thread).
// ---------------------------------------------------------------------------

#if defined(__CUDA_ARCH_FEAT_SM103_ALL)
#define TCG_ENABLED 1
#else
#define TCG_ENABLED 0
#endif

#define TOK 65536
#define NWIN 1024

// scratch (device globals: allocation-free)
__device__ float g_t  [TOK * 256];
__device__ float g_h  [TOK * 256];
__device__ float g_qkv[TOK * 768];
__device__ float g_o  [TOK * 256];
__device__ float g_mlp[TOK * 1024];
__device__ float g_bp [2 * 8 * 64 * 64];
__device__ float g_wtf[1638400];       // tf32-rounded, TRANSPOSED weights [N,K]

#define WOFF_PATCH 0
#define WOFF_QKV   65536
#define WOFF_OUT   458752
#define WOFF_W1    589824
#define WOFF_W2    1114112

__device__ __forceinline__ unsigned f2tf(float f)
{
    unsigned u;
    asm("cvt.rna.tf32.f32 %0, %1;" : "=r"(u) : "f"(f));
    return u;
}
__device__ __forceinline__ float rtf(float f) { return __uint_as_float(f2tf(f)); }

// ---------------------------------------------------------------------------
// weight transpose + tf32 round:  src[K,N] -> dst[N,K]
// ---------------------------------------------------------------------------
__global__ void wtT_kernel(const float* __restrict__ src, float* __restrict__ dst,
                           int K, int N)
{
    __shared__ float s[32][33];
    int n0 = blockIdx.x * 32, k0 = blockIdx.y * 32;
    int tx = threadIdx.x, ty = threadIdx.y;
#pragma unroll
    for (int i = 0; i < 4; i++)
        s[ty + i * 8][tx] = src[(size_t)(k0 + ty + i * 8) * N + n0 + tx];
    __syncthreads();
#pragma unroll
    for (int i = 0; i < 4; i++)
        dst[(size_t)(n0 + ty + i * 8) * K + k0 + tx] = rtf(s[tx][ty + i * 8]);
}

// ---------------------------------------------------------------------------
// window partition gather:  x[B,C,H,W] -> xg[token, C]   (tf32-rounded)
// ---------------------------------------------------------------------------
__global__ void gather_kernel(const float* __restrict__ x, float* __restrict__ xg)
{
    __shared__ float s[32][33];
    int bh = blockIdx.z; int b = bh >> 7; int h = bh & 127;
    int w0 = blockIdx.x * 32, c0 = blockIdx.y * 32;
    int tx = threadIdx.x, ty = threadIdx.y;
#pragma unroll
    for (int i = 0; i < 4; i++) {
        int ch = c0 + ty + i * 8;
        s[ty + i * 8][tx] = x[(((size_t)b * 256 + ch) * 128 + h) * 128 + w0 + tx];
    }
    __syncthreads();
    int wh = h >> 3, r = h & 7;
#pragma unroll
    for (int i = 0; i < 4; i++) {
        int w = w0 + ty + i * 8;
        int row = ((b * 16 + wh) * 16 + (w >> 3)) * 64 + r * 8 + (w & 7);
        xg[(size_t)row * 256 + c0 + tx] = rtf(s[tx][ty + i * 8]);
    }
}

__global__ void reverse_kernel(const float* __restrict__ t, float* __restrict__ out)
{
    __shared__ float s[32][33];
    int bh = blockIdx.z; int b = bh >> 7; int h = bh & 127;
    int w0 = blockIdx.x * 32, d0 = blockIdx.y * 32;
    int tx = threadIdx.x, ty = threadIdx.y;
    int wh = h >> 3, r = h & 7;
#pragma unroll
    for (int i = 0; i < 4; i++) {
        int w = w0 + ty + i * 8;
        int row = ((b * 16 + wh) * 16 + (w >> 3)) * 64 + r * 8 + (w & 7);
        s[ty + i * 8][tx] = t[(size_t)row * 256 + d0 + tx];
    }
    __syncthreads();
#pragma unroll
    for (int i = 0; i < 4; i++) {
        int d = d0 + ty + i * 8;
        out[(((size_t)b * 256 + d) * 128 + h) * 128 + w0 + tx] = s[tx][ty + i * 8];
    }
}

// ---------------------------------------------------------------------------
// tcgen05 tf32 SS GEMM: C[M,N] = A[M,K] @ Bt[N,K]^T (+bias)(+relu)(+resid)(+round)
// CTA tile 128x128, K chunks of 32, 3-stage cp.async pipeline, 128 threads.
// Stage layout (A and B identical): 128 rows x 32 tf32 (128B/row), SW128,
// SBO=64/LBO=1 (byte-identical to the validated test_2cta_mma_bf16 tile);
// k8 advance = +2 descriptor units (32B), per test_mma_iter.
// ---------------------------------------------------------------------------
#define TCG_STAGES 3
#define TCG_STAGE_BYTES 32768            // A 16KB + B 16KB
#define TCG_SMEM (1024 + TCG_STAGES * TCG_STAGE_BYTES + 64)

// idesc: F32 accum(0x10) | atype TF32(2<<7) | btype TF32(2<<10) | N/8<<17 | M/16<<24
#define TCG_IDESC 0x8200910u

__device__ __forceinline__ uint32_t swz(uint32_t off) { return off ^ ((off >> 3) & 0x70); }

__device__ __forceinline__ void cp16s(uint32_t daddr, const float* src)
{
    asm volatile("cp.async.cg.shared.global [%0], [%1], 16;" :: "r"(daddr), "l"(src));
}

__device__ __forceinline__ uint64_t mk_desc(uint32_t addr)
{
    return (2ULL << 61) | (1ULL << 46) | (64ULL << 32) | (1ULL << 16)
         | ((uint64_t)(addr >> 4) & 0x3FFF);
}

template<bool HAS_BIAS, bool RELU, bool RES, bool ROUND>
__global__ void __launch_bounds__(128)
tcgemm_kernel(const float* __restrict__ A, const float* __restrict__ Bt,
              const float* __restrict__ bias, const float* __restrict__ resid,
              float* __restrict__ C, int M, int N, int K)
{
#if TCG_ENABLED
    extern __shared__ char smem_raw[];
    uint32_t sbase;
    asm("{ .reg .u64 t; cvta.to.shared.u64 t, %1; cvt.u32.u64 %0, t; }"
        : "=r"(sbase) : "l"(smem_raw));
    uint32_t base1k = (sbase + 1023u) & ~1023u;
    uint32_t ctrl   = base1k + TCG_STAGES * TCG_STAGE_BYTES;   // tmem ptr, then 3 mbars

    int tid = threadIdx.x;
    int bm = blockIdx.y * 128, bn = blockIdx.x * 128;

    if (tid < 32) {
        asm volatile("tcgen05.alloc.cta_group::1.sync.aligned.shared::cta.b32 [%0], %1;"
                     :: "r"(ctrl), "r"(128u) : "memory");
        asm volatile("tcgen05.relinquish_alloc_permit.cta_group::1.sync.aligned;");
    }
    if (tid == 0) {
#pragma unroll
        for (int s = 0; s < TCG_STAGES; s++)
            asm volatile("mbarrier.init.shared.b64 [%0], %1;"
                         :: "r"(ctrl + 16 + s * 8), "r"(1u) : "memory");
    }
    __syncthreads();
    uint32_t tmem_d;
    asm volatile("ld.shared.b32 %0, [%1];" : "=r"(tmem_d) : "r"(ctrl));

    int nchunks = K >> 5;

    const float* Abase = A  + (size_t)(bm + tid) * K;
    const float* Bbase = Bt + (size_t)(bn + tid) * K;
    uint32_t roff[8];
#pragma unroll
    for (int kk = 0; kk < 8; kk++) roff[kk] = swz((uint32_t)tid * 128 + kk * 16);

    // prologue: chunks 0,1 into stages 0,1  (full row: 8x16B per operand)
#pragma unroll
    for (int pt = 0; pt < 2; pt++) {
        uint32_t aS = base1k + pt * TCG_STAGE_BYTES;
        uint32_t bS = aS + 16384;
        const float* a0 = Abase + pt * 32;
        const float* b0 = Bbase + pt * 32;
#pragma unroll
        for (int kk = 0; kk < 8; kk++) {
            cp16s(aS + roff[kk], a0 + kk * 4);
            cp16s(bS + roff[kk], b0 + kk * 4);
        }
        asm volatile("cp.async.commit_group;");
    }

    for (int c = 0; c < nchunks; c++) {
        int s = c % 3;
        asm volatile("cp.async.wait_group 1;");
        asm volatile("fence.proxy.async.shared::cta;" ::: "memory");
        __syncthreads();

        if (tid == 0) {
            uint32_t aS = base1k + s * TCG_STAGE_BYTES;
            uint64_t ad = mk_desc(aS);
            uint64_t bd = mk_desc(aS + 16384);
#pragma unroll
            for (int kc = 0; kc < 4; kc++) {
                uint32_t en = (c > 0 || kc > 0) ? 1u : 0u;
                uint64_t a_desc = ad + kc * 2, b_desc = bd + kc * 2;
                asm volatile(
                    "{\n\t"
                    ".reg .pred p;\n\t"
                    "setp.ne.u32 p, %5, 0;\n\t"
                    "tcgen05.mma.cta_group::1.kind::tf32 [%0], %1, %2, %3, {%4, %4, %4, %4}, p;\n\t"
                    "}"
                    :: "r"(tmem_d), "l"(a_desc), "l"(b_desc), "r"(TCG_IDESC), "r"(0u), "r"(en)
                    : "memory");
            }
            asm volatile(
                "tcgen05.commit.cta_group::1.mbarrier::arrive::one.shared::cluster.b64 [%0];"
                :: "r"(ctrl + 16 + s * 8) : "memory");
        }

        // stage being refilled next holds chunk c-1's data -> wait its MMA (lagged)
        if (c >= 1) {
            int cw = c - 1;
            uint32_t mb = ctrl + 16 + (cw % 3) * 8;
            uint32_t pr = (uint32_t)((cw / 3) & 1);
            asm volatile(
                "{\n\t"
                ".reg .pred P;\n\t"
                "W_%=: \n\t"
                "mbarrier.try_wait.parity.acquire.cta.shared::cta.b64 P, [%0], %1, 0x989680;\n\t"
                "@!P bra W_%=;\n\t"
                "}"
                :: "r"(mb), "r"(pr) : "memory");
        }
        if (c + 2 < nchunks) {
            int s2 = (c + 2) % 3;
            uint32_t aS = base1k + s2 * TCG_STAGE_BYTES;
            uint32_t bS = aS + 16384;
            const float* a0 = Abase + (size_t)(c + 2) * 32;
            const float* b0 = Bbase + (size_t)(c + 2) * 32;
#pragma unroll
            for (int kk = 0; kk < 8; kk++) {
                cp16s(aS + roff[kk], a0 + kk * 4);
                cp16s(bS + roff[kk], b0 + kk * 4);
            }
        }
        asm volatile("cp.async.commit_group;");
    }

    // wait last chunk's MMA
    {
        int cw = nchunks - 1;
        uint32_t mb = ctrl + 16 + (cw % 3) * 8;
        uint32_t pr = (uint32_t)((cw / 3) & 1);
        asm volatile(
            "{\n\t"
            ".reg .pred P;\n\t"
            "W_%=: \n\t"
            "mbarrier.try_wait.parity.acquire.cta.shared::cta.b64 P, [%0], %1, 0x989680;\n\t"
            "@!P bra W_%=;\n\t"
            "}"
            :: "r"(mb), "r"(pr) : "memory");
    }
    asm volatile("tcgen05.fence::after_thread_sync;" ::: "memory");

    // epilogue: 4 chunks of 32 cols; LDTM -> smem stage -> coalesced stores
    float* eb = (float*)(smem_raw + (base1k - sbase));
    int wid = tid >> 5, lane = tid & 31;
#pragma unroll
    for (int off = 0; off < 128; off += 32) {
        uint32_t r[32];
        asm volatile(
            "tcgen05.ld.sync.aligned.32x32b.x32.b32 "
            "{%0, %1, %2, %3, %4, %5, %6, %7, "
            " %8, %9, %10, %11, %12, %13, %14, %15, "
            " %16, %17, %18, %19, %20, %21, %22, %23, "
            " %24, %25, %26, %27, %28, %29, %30, %31}, [%32];"
            : "=r"(r[0]),  "=r"(r[1]),  "=r"(r[2]),  "=r"(r[3]),
              "=r"(r[4]),  "=r"(r[5]),  "=r"(r[6]),  "=r"(r[7]),
              "=r"(r[8]),  "=r"(r[9]),  "=r"(r[10]), "=r"(r[11]),
              "=r"(r[12]), "=r"(r[13]), "=r"(r[14]), "=r"(r[15]),
              "=r"(r[16]), "=r"(r[17]), "=r"(r[18]), "=r"(r[19]),
              "=r"(r[20]), "=r"(r[21]), "=r"(r[22]), "=r"(r[23]),
              "=r"(r[24]), "=r"(r[25]), "=r"(r[26]), "=r"(r[27]),
              "=r"(r[28]), "=r"(r[29]), "=r"(r[30]), "=r"(r[31])
            : "r"(tmem_d + off));
        asm volatile("tcgen05.wait::ld.sync.aligned;" ::: "memory");

        int myrow = wid * 32 + lane;
#pragma unroll
        for (int cc = 0; cc < 32; cc++)
            eb[myrow * 33 + cc] = __uint_as_float(r[cc]);
        __syncthreads();

#pragma unroll 4
        for (int p = 0; p < 32; p++) {
            int row = p * 4 + wid;
            int col = lane;
            float v = eb[row * 33 + col];
            int gcol = bn + off + col;
            if (HAS_BIAS) v += bias[gcol];
            if (RELU)     v = fmaxf(v, 0.f);
            if (RES)      v += resid[(size_t)(bm + row) * N + gcol];
            if (ROUND)    v = rtf(v);
            C[(size_t)(bm + row) * N + gcol] = v;
        }
        __syncthreads();
    }

    if (tid == 0) {
#pragma unroll
        for (int s = 0; s < TCG_STAGES; s++)
            asm volatile("mbarrier.inval.shared.b64 [%0];" :: "r"(ctrl + 16 + s * 8) : "memory");
    }
    if (tid < 32) {
        asm volatile("tcgen05.dealloc.cta_group::1.sync.aligned.b32 %0, %1;"
                     :: "r"(tmem_d), "r"(128u));
    }
#else
    // -------- generic-arch fallback (correct, slow; should not run on GB300) --------
    extern __shared__ float fsm[];
    int tid = threadIdx.x;
    int bm = blockIdx.y * 128, bn = blockIdx.x * 128;
    int row = bm + tid;
    float acc[128];
#pragma unroll
    for (int c = 0; c < 128; c++) acc[c] = 0.f;
    for (int k0 = 0; k0 < K; k0 += 32) {
        const float* br = Bt + (size_t)(bn + tid) * K + k0;
#pragma unroll
        for (int kk = 0; kk < 32; kk += 4)
            *(float4*)(&fsm[tid * 32 + kk]) = *(const float4*)(br + kk);
        __syncthreads();
        float a[32];
        const float* ar = A + (size_t)row * K + k0;
#pragma unroll
        for (int kk = 0; kk < 32; kk++) a[kk] = ar[kk];
        for (int c = 0; c < 128; c++) {
            float s = acc[c];
#pragma unroll
            for (int kk = 0; kk < 32; kk++) s += a[kk] * fsm[c * 32 + kk];
            acc[c] = s;
        }
        __syncthreads();
    }
    for (int c = 0; c < 128; c++) {
        float v = acc[c];
        int gcol = bn + c;
        if (HAS_BIAS) v += bias[gcol];
        if (RELU)     v = fmaxf(v, 0.f);
        if (RES)      v += resid[(size_t)row * N + gcol];
        if (ROUND)    v = rtf(v);
        C[(size_t)row * N + gcol] = v;
    }
#endif
}

// ---------------------------------------------------------------------------
// LayerNorm: one warp per row of 256   (tf32-rounded output)
// ---------------------------------------------------------------------------
__global__ void ln_kernel(const float* __restrict__ x, const float* __restrict__ g,
                          const float* __restrict__ b, float* __restrict__ y)
{
    int row  = blockIdx.x * 8 + threadIdx.y;
    int lane = threadIdx.x;
    const float* xr = x + (size_t)row * 256;
    float v[8]; float s = 0.f, s2 = 0.f;
#pragma unroll
    for (int i = 0; i < 8; i++) {
        v[i] = xr[lane + i * 32];
        s  += v[i];
        s2 += v[i] * v[i];
    }
#pragma unroll
    for (int o = 16; o; o >>= 1) {
        s  += __shfl_xor_sync(0xffffffffu, s,  o);
        s2 += __shfl_xor_sync(0xffffffffu, s2, o);
    }
    float mean = s * (1.f / 256.f);
    float var  = s2 * (1.f / 256.f) - mean * mean;
    float inv  = rsqrtf(var + 1e-5f);
#pragma unroll
    for (int i = 0; i < 8; i++) {
        int c = lane + i * 32;
        y[(size_t)row * 256 + c] = rtf((v[i] - mean) * inv * g[c] + b[c]);
    }
}

// ---------------------------------------------------------------------------
// precompute bias + 0.01 * gaussian decay per (layer, head): g_bp
// ---------------------------------------------------------------------------
__global__ void bp_kernel(const float* __restrict__ bias_table,
                          const float* __restrict__ headsita)
{
    int l = blockIdx.y, head = blockIdx.x;
    int i = threadIdx.x;
    float sita   = headsita[l * 8 + head];
    float factor = 1.0f / (2.0f * sita * sita + 1e-10f);
    int ih = i >> 3, iw = i & 7;
    for (int j = 0; j < 64; j++) {
        int jh = j >> 3, jw = j & 7;
        int dh = ih - jh, dw = iw - jw;
        float fh = (float)dh * 0.125f, fw = (float)dw * 0.125f;
        float dis = fh * fh + fw * fw;
        int rpi = (dh + 7) * 15 + (dw + 7);
        float bv = bias_table[((size_t)l * 225 + rpi) * 8 + head];
        g_bp[(((size_t)l * 8 + head) * 64 + i) * 64 + j] = bv + 0.01f * __expf(-factor * dis);
    }
}

// ---------------------------------------------------------------------------
// attention per (window, head): 64 threads, thread i owns query row i.
// ---------------------------------------------------------------------------
__global__ void __launch_bounds__(64)
attn_kernel(const float* __restrict__ qkv, float* __restrict__ attns_out,
            float* __restrict__ obuf, int layer)
{
    const float SCALE = 0.17677669529663689f;  // 32^-0.5
    int head = blockIdx.x;
    int win  = blockIdx.y;
    int i    = threadIdx.x;

    __shared__ float ks[64][32];
    __shared__ float vs[64][32];

    const float* base = qkv + (size_t)win * 64 * 768 + head * 32;
    float q[32];
#pragma unroll
    for (int d = 0; d < 32; d++) q[d]      = base[(size_t)i * 768 + d];
#pragma unroll
    for (int d = 0; d < 32; d++) ks[i][d]  = base[(size_t)i * 768 + 256 + d];
#pragma unroll
    for (int d = 0; d < 32; d++) vs[i][d]  = base[(size_t)i * 768 + 512 + d];
    __syncthreads();

    float dots[64];
#pragma unroll 4
    for (int j = 0; j < 64; j++) {
        float s = 0.f;
#pragma unroll
        for (int d = 0; d < 32; d++) s += q[d] * ks[j][d];
        dots[j] = s * SCALE;
    }

    float m0 = -1e30f;
#pragma unroll
    for (int j = 0; j < 64; j++) m0 = fmaxf(m0, dots[j]);
    float sum0 = 0.f;
#pragma unroll
    for (int j = 0; j < 64; j++) sum0 += __expf(dots[j] - m0);
    float inv0 = 1.f / sum0;
    float* arow = attns_out + (((size_t)layer * NWIN + win) * 8 + head) * 4096 + (size_t)i * 64;
#pragma unroll
    for (int j = 0; j < 64; j++) arow[j] = __expf(dots[j] - m0) * inv0;

    const float* bp = g_bp + (((size_t)layer * 8 + head) * 64 + i) * 64;
#pragma unroll
    for (int j = 0; j < 64; j++) dots[j] += bp[j];
    float m1 = -1e30f;
#pragma unroll
    for (int j = 0; j < 64; j++) m1 = fmaxf(m1, dots[j]);
    float sum1 = 0.f;
#pragma unroll
    for (int j = 0; j < 64; j++) { dots[j] = __expf(dots[j] - m1); sum1 += dots[j]; }
    float inv1 = 1.f / sum1;

    float acc[32];
#pragma unroll
    for (int d = 0; d < 32; d++) acc[d] = 0.f;
#pragma unroll 4
    for (int j = 0; j < 64; j++) {
        float a = dots[j] * inv1;
#pragma unroll
        for (int d = 0; d < 32; d++) acc[d] += a * vs[j][d];
    }
    float* orow = obuf + (size_t)(win * 64 + i) * 256 + head * 32;
#pragma unroll
    for (int d = 0; d < 32; d++) orow[d] = rtf(acc[d]);
}

// ---------------------------------------------------------------------------
extern "C" void kernel_launch(void* const* d_in, const int* in_sizes, int n_in,
                              void* d_out, int out_size)
{
    const float* x          = (const float*)d_in[0];
    const float* W_patch    = (const float*)d_in[1];
    const float* b_patch    = (const float*)d_in[2];
    const float* ln1_g      = (const float*)d_in[3];
    const float* ln1_b      = (const float*)d_in[4];
    const float* Wqkv       = (const float*)d_in[5];
    const float* headsita   = (const float*)d_in[6];
    const float* bias_table = (const float*)d_in[7];
    const float* Wout       = (const float*)d_in[8];
    const float* bout       = (const float*)d_in[9];
    const float* ln2_g      = (const float*)d_in[10];
    const float* ln2_b      = (const float*)d_in[11];
    const float* W1         = (const float*)d_in[12];
    const float* b1         = (const float*)d_in[13];
    const float* W2         = (const float*)d_in[14];
    const float* b2         = (const float*)d_in[15];

    float* out   = (float*)d_out;
    float* attns = out + (size_t)16777216;

    float *t, *h, *qkvb, *ob, *mlpb, *wtf;
    cudaGetSymbolAddress((void**)&t,    g_t);
    cudaGetSymbolAddress((void**)&h,    g_h);
    cudaGetSymbolAddress((void**)&qkvb, g_qkv);
    cudaGetSymbolAddress((void**)&ob,   g_o);
    cudaGetSymbolAddress((void**)&mlpb, g_mlp);
    cudaGetSymbolAddress((void**)&wtf,  g_wtf);

    static bool attr_done = false;
    if (!attr_done) {
        cudaFuncSetAttribute(tcgemm_kernel<true,  false, false, false>, cudaFuncAttributeMaxDynamicSharedMemorySize, TCG_SMEM);
        cudaFuncSetAttribute(tcgemm_kernel<false, false, false, false>, cudaFuncAttributeMaxDynamicSharedMemorySize, TCG_SMEM);
        cudaFuncSetAttribute(tcgemm_kernel<true,  false, true,  false>, cudaFuncAttributeMaxDynamicSharedMemorySize, TCG_SMEM);
        cudaFuncSetAttribute(tcgemm_kernel<true,  true,  false, true >, cudaFuncAttributeMaxDynamicSharedMemorySize, TCG_SMEM);
        attr_done = true;
    }

    dim3 tb32x8(32, 8);
    dim3 g_gather(4, 8, 512);

    // transpose + tf32-round all weights: W[K,N] -> Wt[N,K]
    wtT_kernel<<<dim3(8,  8), tb32x8>>>(W_patch, wtf + WOFF_PATCH, 256, 256);
    for (int l = 0; l < 2; l++) {
        wtT_kernel<<<dim3(24, 8), tb32x8>>>(Wqkv + (size_t)l * 196608, wtf + WOFF_QKV + (size_t)l * 196608, 256, 768);
        wtT_kernel<<<dim3(8,  8), tb32x8>>>(Wout + (size_t)l * 65536,  wtf + WOFF_OUT + (size_t)l * 65536,  256, 256);
        wtT_kernel<<<dim3(32, 8), tb32x8>>>(W1   + (size_t)l * 262144, wtf + WOFF_W1  + (size_t)l * 262144, 256, 1024);
        wtT_kernel<<<dim3(8, 32), tb32x8>>>(W2   + (size_t)l * 262144, wtf + WOFF_W2  + (size_t)l * 262144, 1024, 256);
    }

    gather_kernel<<<g_gather, tb32x8>>>(x, h);

    tcgemm_kernel<true, false, false, false><<<dim3(2, 512), 128, TCG_SMEM>>>(h, wtf + WOFF_PATCH, b_patch, nullptr, t, TOK, 256, 256);

    bp_kernel<<<dim3(8, 2), 64>>>(bias_table, headsita);

    for (int l = 0; l < 2; l++) {
        ln_kernel<<<8192, tb32x8>>>(t, ln1_g + l * 256, ln1_b + l * 256, h);
        tcgemm_kernel<false, false, false, false><<<dim3(6, 512), 128, TCG_SMEM>>>(h, wtf + WOFF_QKV + (size_t)l * 196608, nullptr, nullptr, qkvb, TOK, 768, 256);
        attn_kernel<<<dim3(8, NWIN), 64>>>(qkvb, attns, ob, l);
        tcgemm_kernel<true, false, true, false><<<dim3(2, 512), 128, TCG_SMEM>>>(ob, wtf + WOFF_OUT + (size_t)l * 65536, bout + l * 256, t, t, TOK, 256, 256);
        ln_kernel<<<8192, tb32x8>>>(t, ln2_g + l * 256, ln2_b + l * 256, h);
        tcgemm_kernel<true, true, false, true><<<dim3(8, 512), 128, TCG_SMEM>>>(h, wtf + WOFF_W1 + (size_t)l * 262144, b1 + l * 1024, nullptr, mlpb, TOK, 1024, 256);
        tcgemm_kernel<true, false, true, false><<<dim3(2, 512), 128, TCG_SMEM>>>(mlpb, wtf + WOFF_W2 + (size_t)l * 262144, b2 + l * 256, t, t, TOK, 256, 1024);
    }

    reverse_kernel<<<g_gather, tb32x8>>>(t, out);
}

// round 14
// speedup vs baseline: 1.1518x; 1.1518x over previous
#include <cuda_runtime.h>
#include <cuda_bf16.h>
#include <math.h>
#include <stdint.h>

// ---------------------------------------------------------------------------
// StandardPartitionAttention  (Swin-style window attention, DEPTH=2)
// R14: tcgen05 tf32 GEMM with 128x256 CTA tile (N=256 MMA atom), 256 threads,
//      3-stage cp.async pipeline, TMEM 256-col accumulator. Overhead per
//      k-chunk amortized over 4x the MMA work vs R13.
// ---------------------------------------------------------------------------

#if defined(__CUDA_ARCH_FEAT_SM103_ALL)
#define TCG_ENABLED 1
#else
#define TCG_ENABLED 0
#endif

#define TOK 65536
#define NWIN 1024

// scratch (device globals: allocation-free)
__device__ float g_t  [TOK * 256];
__device__ float g_h  [TOK * 256];
__device__ float g_qkv[TOK * 768];
__device__ float g_o  [TOK * 256];
__device__ float g_mlp[TOK * 1024];
__device__ float g_bp [2 * 8 * 64 * 64];
__device__ float g_wtf[1638400];       // tf32-rounded, TRANSPOSED weights [N,K]

#define WOFF_PATCH 0
#define WOFF_QKV   65536
#define WOFF_OUT   458752
#define WOFF_W1    589824
#define WOFF_W2    1114112

__device__ __forceinline__ unsigned f2tf(float f)
{
    unsigned u;
    asm("cvt.rna.tf32.f32 %0, %1;" : "=r"(u) : "f"(f));
    return u;
}
__device__ __forceinline__ float rtf(float f) { return __uint_as_float(f2tf(f)); }

// ---------------------------------------------------------------------------
// weight transpose + tf32 round:  src[K,N] -> dst[N,K]
// ---------------------------------------------------------------------------
__global__ void wtT_kernel(const float* __restrict__ src, float* __restrict__ dst,
                           int K, int N)
{
    __shared__ float s[32][33];
    int n0 = blockIdx.x * 32, k0 = blockIdx.y * 32;
    int tx = threadIdx.x, ty = threadIdx.y;
#pragma unroll
    for (int i = 0; i < 4; i++)
        s[ty + i * 8][tx] = src[(size_t)(k0 + ty + i * 8) * N + n0 + tx];
    __syncthreads();
#pragma unroll
    for (int i = 0; i < 4; i++)
        dst[(size_t)(n0 + ty + i * 8) * K + k0 + tx] = rtf(s[tx][ty + i * 8]);
}

// ---------------------------------------------------------------------------
// window partition gather:  x[B,C,H,W] -> xg[token, C]   (tf32-rounded)
// ---------------------------------------------------------------------------
__global__ void gather_kernel(const float* __restrict__ x, float* __restrict__ xg)
{
    __shared__ float s[32][33];
    int bh = blockIdx.z; int b = bh >> 7; int h = bh & 127;
    int w0 = blockIdx.x * 32, c0 = blockIdx.y * 32;
    int tx = threadIdx.x, ty = threadIdx.y;
#pragma unroll
    for (int i = 0; i < 4; i++) {
        int ch = c0 + ty + i * 8;
        s[ty + i * 8][tx] = x[(((size_t)b * 256 + ch) * 128 + h) * 128 + w0 + tx];
    }
    __syncthreads();
    int wh = h >> 3, r = h & 7;
#pragma unroll
    for (int i = 0; i < 4; i++) {
        int w = w0 + ty + i * 8;
        int row = ((b * 16 + wh) * 16 + (w >> 3)) * 64 + r * 8 + (w & 7);
        xg[(size_t)row * 256 + c0 + tx] = rtf(s[tx][ty + i * 8]);
    }
}

__global__ void reverse_kernel(const float* __restrict__ t, float* __restrict__ out)
{
    __shared__ float s[32][33];
    int bh = blockIdx.z; int b = bh >> 7; int h = bh & 127;
    int w0 = blockIdx.x * 32, d0 = blockIdx.y * 32;
    int tx = threadIdx.x, ty = threadIdx.y;
    int wh = h >> 3, r = h & 7;
#pragma unroll
    for (int i = 0; i < 4; i++) {
        int w = w0 + ty + i * 8;
        int row = ((b * 16 + wh) * 16 + (w >> 3)) * 64 + r * 8 + (w & 7);
        s[ty + i * 8][tx] = t[(size_t)row * 256 + d0 + tx];
    }
    __syncthreads();
#pragma unroll
    for (int i = 0; i < 4; i++) {
        int d = d0 + ty + i * 8;
        out[(((size_t)b * 256 + d) * 128 + h) * 128 + w0 + tx] = s[tx][ty + i * 8];
    }
}

// ---------------------------------------------------------------------------
// tcgen05 tf32 SS GEMM: C[M,N] = A[M,K] @ Bt[N,K]^T (+bias)(+relu)(+resid)(+round)
// CTA tile 128x256, K chunks of 32, 3-stage cp.async pipeline, 256 threads.
// Per stage: A 128 rows x 128B (16KB) + B 256 rows x 128B (32KB), SW128,
// SBO=64/LBO=1; k8 advance = +2 descriptor units (32B). N=256 single MMA atom.
// ---------------------------------------------------------------------------
#define TCG_STAGES 3
#define TCG_A_BYTES 16384
#define TCG_B_BYTES 32768
#define TCG_STAGE_BYTES (TCG_A_BYTES + TCG_B_BYTES)      // 48KB
#define TCG_SMEM (1024 + TCG_STAGES * TCG_STAGE_BYTES + 64)

// idesc: F32 accum(0x10) | atype TF32(2<<7) | btype TF32(2<<10) | (256/8)<<17 | (128/16)<<24
#define TCG_IDESC 0x8400910u

__device__ __forceinline__ uint32_t swz(uint32_t off) { return off ^ ((off >> 3) & 0x70); }

__device__ __forceinline__ void cp16s(uint32_t daddr, const float* src)
{
    asm volatile("cp.async.cg.shared.global [%0], [%1], 16;" :: "r"(daddr), "l"(src));
}

__device__ __forceinline__ uint64_t mk_desc(uint32_t addr)
{
    return (2ULL << 61) | (1ULL << 46) | (64ULL << 32) | (1ULL << 16)
         | ((uint64_t)(addr >> 4) & 0x3FFF);
}

template<bool HAS_BIAS, bool RELU, bool RES, bool ROUND>
__global__ void __launch_bounds__(256)
tcgemm_kernel(const float* __restrict__ A, const float* __restrict__ Bt,
              const float* __restrict__ bias, const float* __restrict__ resid,
              float* __restrict__ C, int M, int N, int K)
{
#if TCG_ENABLED
    extern __shared__ char smem_raw[];
    uint32_t sbase;
    asm("{ .reg .u64 t; cvta.to.shared.u64 t, %1; cvt.u32.u64 %0, t; }"
        : "=r"(sbase) : "l"(smem_raw));
    uint32_t base1k = (sbase + 1023u) & ~1023u;
    uint32_t ctrl   = base1k + TCG_STAGES * TCG_STAGE_BYTES;   // tmem ptr, then 3 mbars

    int tid = threadIdx.x;
    int bm = blockIdx.y * 128, bn = blockIdx.x * 256;

    if (tid < 32) {
        asm volatile("tcgen05.alloc.cta_group::1.sync.aligned.shared::cta.b32 [%0], %1;"
                     :: "r"(ctrl), "r"(256u) : "memory");
        asm volatile("tcgen05.relinquish_alloc_permit.cta_group::1.sync.aligned;");
    }
    if (tid == 0) {
#pragma unroll
        for (int s = 0; s < TCG_STAGES; s++)
            asm volatile("mbarrier.init.shared.b64 [%0], %1;"
                         :: "r"(ctrl + 16 + s * 8), "r"(1u) : "memory");
    }
    __syncthreads();
    uint32_t tmem_d;
    asm volatile("ld.shared.b32 %0, [%1];" : "=r"(tmem_d) : "r"(ctrl));

    int nchunks = K >> 5;

    // A: thread t covers row t>>1, 64B half (t&1): 4 cp16.
    // B: thread t covers row t (0..255), full 128B: 8 cp16.
    int a_row = tid >> 1, a_half = (tid & 1) * 64;
    const float* Abase = A  + (size_t)(bm + a_row) * K + (tid & 1) * 16;
    const float* Bbase = Bt + (size_t)(bn + tid) * K;
    uint32_t aoff[4], boff[8];
#pragma unroll
    for (int kk = 0; kk < 4; kk++) aoff[kk] = swz((uint32_t)a_row * 128 + a_half + kk * 16);
#pragma unroll
    for (int kk = 0; kk < 8; kk++) boff[kk] = swz((uint32_t)tid * 128 + kk * 16);

    // prologue: chunks 0,1 into stages 0,1
#pragma unroll
    for (int pt = 0; pt < 2; pt++) {
        uint32_t aS = base1k + pt * TCG_STAGE_BYTES;
        uint32_t bS = aS + TCG_A_BYTES;
        const float* a0 = Abase + pt * 32;
        const float* b0 = Bbase + pt * 32;
#pragma unroll
        for (int kk = 0; kk < 4; kk++) cp16s(aS + aoff[kk], a0 + kk * 4);
#pragma unroll
        for (int kk = 0; kk < 8; kk++) cp16s(bS + boff[kk], b0 + kk * 4);
        asm volatile("cp.async.commit_group;");
    }

    for (int c = 0; c < nchunks; c++) {
        int s = c % 3;
        asm volatile("cp.async.wait_group 1;");
        asm volatile("fence.proxy.async.shared::cta;" ::: "memory");
        __syncthreads();

        if (tid == 0) {
            uint32_t aS = base1k + s * TCG_STAGE_BYTES;
            uint64_t ad = mk_desc(aS);
            uint64_t bd = mk_desc(aS + TCG_A_BYTES);
#pragma unroll
            for (int kc = 0; kc < 4; kc++) {
                uint32_t en = (c > 0 || kc > 0) ? 1u : 0u;
                uint64_t a_desc = ad + kc * 2, b_desc = bd + kc * 2;
                asm volatile(
                    "{\n\t"
                    ".reg .pred p;\n\t"
                    "setp.ne.u32 p, %5, 0;\n\t"
                    "tcgen05.mma.cta_group::1.kind::tf32 [%0], %1, %2, %3, {%4, %4, %4, %4}, p;\n\t"
                    "}"
                    :: "r"(tmem_d), "l"(a_desc), "l"(b_desc), "r"(TCG_IDESC), "r"(0u), "r"(en)
                    : "memory");
            }
            asm volatile(
                "tcgen05.commit.cta_group::1.mbarrier::arrive::one.shared::cluster.b64 [%0];"
                :: "r"(ctrl + 16 + s * 8) : "memory");
        }

        // stage refilled next holds chunk c-1's data -> wait its MMA (lagged)
        if (c >= 1) {
            int cw = c - 1;
            uint32_t mb = ctrl + 16 + (cw % 3) * 8;
            uint32_t pr = (uint32_t)((cw / 3) & 1);
            asm volatile(
                "{\n\t"
                ".reg .pred P;\n\t"
                "W_%=: \n\t"
                "mbarrier.try_wait.parity.acquire.cta.shared::cta.b64 P, [%0], %1, 0x989680;\n\t"
                "@!P bra W_%=;\n\t"
                "}"
                :: "r"(mb), "r"(pr) : "memory");
        }
        if (c + 2 < nchunks) {
            int s2 = (c + 2) % 3;
            uint32_t aS = base1k + s2 * TCG_STAGE_BYTES;
            uint32_t bS = aS + TCG_A_BYTES;
            const float* a0 = Abase + (size_t)(c + 2) * 32;
            const float* b0 = Bbase + (size_t)(c + 2) * 32;
#pragma unroll
            for (int kk = 0; kk < 4; kk++) cp16s(aS + aoff[kk], a0 + kk * 4);
#pragma unroll
            for (int kk = 0; kk < 8; kk++) cp16s(bS + boff[kk], b0 + kk * 4);
        }
        asm volatile("cp.async.commit_group;");
    }

    // wait last chunk's MMA
    {
        int cw = nchunks - 1;
        uint32_t mb = ctrl + 16 + (cw % 3) * 8;
        uint32_t pr = (uint32_t)((cw / 3) & 1);
        asm volatile(
            "{\n\t"
            ".reg .pred P;\n\t"
            "W_%=: \n\t"
            "mbarrier.try_wait.parity.acquire.cta.shared::cta.b64 P, [%0], %1, 0x989680;\n\t"
            "@!P bra W_%=;\n\t"
            "}"
            :: "r"(mb), "r"(pr) : "memory");
    }
    asm volatile("tcgen05.fence::after_thread_sync;" ::: "memory");

    // epilogue: two warp groups handle col halves; LDTM -> smem -> coalesced stores
    int warp = tid >> 5, lane = tid & 31;
    int group = warp >> 2, wid2 = warp & 3;
    float* eb = (float*)(smem_raw + (base1k - sbase)) + group * (128 * 33);
    uint32_t tcol = tmem_d + group * 128;
#pragma unroll
    for (int off = 0; off < 128; off += 32) {
        uint32_t r[32];
        asm volatile(
            "tcgen05.ld.sync.aligned.32x32b.x32.b32 "
            "{%0, %1, %2, %3, %4, %5, %6, %7, "
            " %8, %9, %10, %11, %12, %13, %14, %15, "
            " %16, %17, %18, %19, %20, %21, %22, %23, "
            " %24, %25, %26, %27, %28, %29, %30, %31}, [%32];"
            : "=r"(r[0]),  "=r"(r[1]),  "=r"(r[2]),  "=r"(r[3]),
              "=r"(r[4]),  "=r"(r[5]),  "=r"(r[6]),  "=r"(r[7]),
              "=r"(r[8]),  "=r"(r[9]),  "=r"(r[10]), "=r"(r[11]),
              "=r"(r[12]), "=r"(r[13]), "=r"(r[14]), "=r"(r[15]),
              "=r"(r[16]), "=r"(r[17]), "=r"(r[18]), "=r"(r[19]),
              "=r"(r[20]), "=r"(r[21]), "=r"(r[22]), "=r"(r[23]),
              "=r"(r[24]), "=r"(r[25]), "=r"(r[26]), "=r"(r[27]),
              "=r"(r[28]), "=r"(r[29]), "=r"(r[30]), "=r"(r[31])
            : "r"(tcol + off));
        asm volatile("tcgen05.wait::ld.sync.aligned;" ::: "memory");

        int myrow = wid2 * 32 + lane;
#pragma unroll
        for (int cc = 0; cc < 32; cc++)
            eb[myrow * 33 + cc] = __uint_as_float(r[cc]);
        __syncthreads();

#pragma unroll 4
        for (int p = 0; p < 32; p++) {
            int row = p * 4 + wid2;
            int gcol = bn + group * 128 + off + lane;
            float v = eb[row * 33 + lane];
            if (HAS_BIAS) v += bias[gcol];
            if (RELU)     v = fmaxf(v, 0.f);
            if (RES)      v += resid[(size_t)(bm + row) * N + gcol];
            if (ROUND)    v = rtf(v);
            C[(size_t)(bm + row) * N + gcol] = v;
        }
        __syncthreads();
    }

    if (tid == 0) {
#pragma unroll
        for (int s = 0; s < TCG_STAGES; s++)
            asm volatile("mbarrier.inval.shared.b64 [%0];" :: "r"(ctrl + 16 + s * 8) : "memory");
    }
    if (tid < 32) {
        asm volatile("tcgen05.dealloc.cta_group::1.sync.aligned.b32 %0, %1;"
                     :: "r"(tmem_d), "r"(256u));
    }
#else
    // -------- generic-arch fallback (correct, slow; never runs on GB300) --------
    extern __shared__ float fsm[];
    int tid = threadIdx.x;
    int bm = blockIdx.y * 128, bn = blockIdx.x * 256;
    int row = bm + (tid >> 1);
    int ch  = (tid & 1) * 128;      // col half
    float acc[128];
#pragma unroll
    for (int c = 0; c < 128; c++) acc[c] = 0.f;
    for (int k0 = 0; k0 < K; k0 += 32) {
        const float* br = Bt + (size_t)(bn + tid) * K + k0;
#pragma unroll
        for (int kk = 0; kk < 32; kk += 4)
            *(float4*)(&fsm[tid * 32 + kk]) = *(const float4*)(br + kk);
        __syncthreads();
        float a[32];
        const float* ar = A + (size_t)row * K + k0;
#pragma unroll
        for (int kk = 0; kk < 32; kk++) a[kk] = ar[kk];
        for (int c = 0; c < 128; c++) {
            float s = acc[c];
#pragma unroll
            for (int kk = 0; kk < 32; kk++) s += a[kk] * fsm[(ch + c) * 32 + kk];
            acc[c] = s;
        }
        __syncthreads();
    }
    for (int c = 0; c < 128; c++) {
        float v = acc[c];
        int gcol = bn + ch + c;
        if (HAS_BIAS) v += bias[gcol];
        if (RELU)     v = fmaxf(v, 0.f);
        if (RES)      v += resid[(size_t)row * N + gcol];
        if (ROUND)    v = rtf(v);
        C[(size_t)row * N + gcol] = v;
    }
#endif
}

// ---------------------------------------------------------------------------
// LayerNorm: one warp per row of 256   (tf32-rounded output)
// ---------------------------------------------------------------------------
__global__ void ln_kernel(const float* __restrict__ x, const float* __restrict__ g,
                          const float* __restrict__ b, float* __restrict__ y)
{
    int row  = blockIdx.x * 8 + threadIdx.y;
    int lane = threadIdx.x;
    const float* xr = x + (size_t)row * 256;
    float v[8]; float s = 0.f, s2 = 0.f;
#pragma unroll
    for (int i = 0; i < 8; i++) {
        v[i] = xr[lane + i * 32];
        s  += v[i];
        s2 += v[i] * v[i];
    }
#pragma unroll
    for (int o = 16; o; o >>= 1) {
        s  += __shfl_xor_sync(0xffffffffu, s,  o);
        s2 += __shfl_xor_sync(0xffffffffu, s2, o);
    }
    float mean = s * (1.f / 256.f);
    float var  = s2 * (1.f / 256.f) - mean * mean;
    float inv  = rsqrtf(var + 1e-5f);
#pragma unroll
    for (int i = 0; i < 8; i++) {
        int c = lane + i * 32;
        y[(size_t)row * 256 + c] = rtf((v[i] - mean) * inv * g[c] + b[c]);
    }
}

// ---------------------------------------------------------------------------
// precompute bias + 0.01 * gaussian decay per (layer, head): g_bp
// ---------------------------------------------------------------------------
__global__ void bp_kernel(const float* __restrict__ bias_table,
                          const float* __restrict__ headsita)
{
    int l = blockIdx.y, head = blockIdx.x;
    int i = threadIdx.x;
    float sita   = headsita[l * 8 + head];
    float factor = 1.0f / (2.0f * sita * sita + 1e-10f);
    int ih = i >> 3, iw = i & 7;
    for (int j = 0; j < 64; j++) {
        int jh = j >> 3, jw = j & 7;
        int dh = ih - jh, dw = iw - jw;
        float fh = (float)dh * 0.125f, fw = (float)dw * 0.125f;
        float dis = fh * fh + fw * fw;
        int rpi = (dh + 7) * 15 + (dw + 7);
        float bv = bias_table[((size_t)l * 225 + rpi) * 8 + head];
        g_bp[(((size_t)l * 8 + head) * 64 + i) * 64 + j] = bv + 0.01f * __expf(-factor * dis);
    }
}

// ---------------------------------------------------------------------------
// attention per (window, head): 64 threads, thread i owns query row i.
// ---------------------------------------------------------------------------
__global__ void __launch_bounds__(64)
attn_kernel(const float* __restrict__ qkv, float* __restrict__ attns_out,
            float* __restrict__ obuf, int layer)
{
    const float SCALE = 0.17677669529663689f;  // 32^-0.5
    int head = blockIdx.x;
    int win  = blockIdx.y;
    int i    = threadIdx.x;

    __shared__ float ks[64][32];
    __shared__ float vs[64][32];

    const float* base = qkv + (size_t)win * 64 * 768 + head * 32;
    float q[32];
#pragma unroll
    for (int d = 0; d < 32; d++) q[d]      = base[(size_t)i * 768 + d];
#pragma unroll
    for (int d = 0; d < 32; d++) ks[i][d]  = base[(size_t)i * 768 + 256 + d];
#pragma unroll
    for (int d = 0; d < 32; d++) vs[i][d]  = base[(size_t)i * 768 + 512 + d];
    __syncthreads();

    float dots[64];
#pragma unroll 4
    for (int j = 0; j < 64; j++) {
        float s = 0.f;
#pragma unroll
        for (int d = 0; d < 32; d++) s += q[d] * ks[j][d];
        dots[j] = s * SCALE;
    }

    float m0 = -1e30f;
#pragma unroll
    for (int j = 0; j < 64; j++) m0 = fmaxf(m0, dots[j]);
    float sum0 = 0.f;
#pragma unroll
    for (int j = 0; j < 64; j++) sum0 += __expf(dots[j] - m0);
    float inv0 = 1.f / sum0;
    float* arow = attns_out + (((size_t)layer * NWIN + win) * 8 + head) * 4096 + (size_t)i * 64;
#pragma unroll
    for (int j = 0; j < 64; j++) arow[j] = __expf(dots[j] - m0) * inv0;

    const float* bp = g_bp + (((size_t)layer * 8 + head) * 64 + i) * 64;
#pragma unroll
    for (int j = 0; j < 64; j++) dots[j] += bp[j];
    float m1 = -1e30f;
#pragma unroll
    for (int j = 0; j < 64; j++) m1 = fmaxf(m1, dots[j]);
    float sum1 = 0.f;
#pragma unroll
    for (int j = 0; j < 64; j++) { dots[j] = __expf(dots[j] - m1); sum1 += dots[j]; }
    float inv1 = 1.f / sum1;

    float acc[32];
#pragma unroll
    for (int d = 0; d < 32; d++) acc[d] = 0.f;
#pragma unroll 4
    for (int j = 0; j < 64; j++) {
        float a = dots[j] * inv1;
#pragma unroll
        for (int d = 0; d < 32; d++) acc[d] += a * vs[j][d];
    }
    float* orow = obuf + (size_t)(win * 64 + i) * 256 + head * 32;
#pragma unroll
    for (int d = 0; d < 32; d++) orow[d] = rtf(acc[d]);
}

// ---------------------------------------------------------------------------
extern "C" void kernel_launch(void* const* d_in, const int* in_sizes, int n_in,
                              void* d_out, int out_size)
{
    const float* x          = (const float*)d_in[0];
    const float* W_patch    = (const float*)d_in[1];
    const float* b_patch    = (const float*)d_in[2];
    const float* ln1_g      = (const float*)d_in[3];
    const float* ln1_b      = (const float*)d_in[4];
    const float* Wqkv       = (const float*)d_in[5];
    const float* headsita   = (const float*)d_in[6];
    const float* bias_table = (const float*)d_in[7];
    const float* Wout       = (const float*)d_in[8];
    const float* bout       = (const float*)d_in[9];
    const float* ln2_g      = (const float*)d_in[10];
    const float* ln2_b      = (const float*)d_in[11];
    const float* W1         = (const float*)d_in[12];
    const float* b1         = (const float*)d_in[13];
    const float* W2         = (const float*)d_in[14];
    const float* b2         = (const float*)d_in[15];

    float* out   = (float*)d_out;
    float* attns = out + (size_t)16777216;

    float *t, *h, *qkvb, *ob, *mlpb, *wtf;
    cudaGetSymbolAddress((void**)&t,    g_t);
    cudaGetSymbolAddress((void**)&h,    g_h);
    cudaGetSymbolAddress((void**)&qkvb, g_qkv);
    cudaGetSymbolAddress((void**)&ob,   g_o);
    cudaGetSymbolAddress((void**)&mlpb, g_mlp);
    cudaGetSymbolAddress((void**)&wtf,  g_wtf);

    static bool attr_done = false;
    if (!attr_done) {
        cudaFuncSetAttribute(tcgemm_kernel<true,  false, false, false>, cudaFuncAttributeMaxDynamicSharedMemorySize, TCG_SMEM);
        cudaFuncSetAttribute(tcgemm_kernel<false, false, false, false>, cudaFuncAttributeMaxDynamicSharedMemorySize, TCG_SMEM);
        cudaFuncSetAttribute(tcgemm_kernel<true,  false, true,  false>, cudaFuncAttributeMaxDynamicSharedMemorySize, TCG_SMEM);
        cudaFuncSetAttribute(tcgemm_kernel<true,  true,  false, true >, cudaFuncAttributeMaxDynamicSharedMemorySize, TCG_SMEM);
        attr_done = true;
    }

    dim3 tb32x8(32, 8);
    dim3 g_gather(4, 8, 512);

    // transpose + tf32-round all weights: W[K,N] -> Wt[N,K]
    wtT_kernel<<<dim3(8,  8), tb32x8>>>(W_patch, wtf + WOFF_PATCH, 256, 256);
    for (int l = 0; l < 2; l++) {
        wtT_kernel<<<dim3(24, 8), tb32x8>>>(Wqkv + (size_t)l * 196608, wtf + WOFF_QKV + (size_t)l * 196608, 256, 768);
        wtT_kernel<<<dim3(8,  8), tb32x8>>>(Wout + (size_t)l * 65536,  wtf + WOFF_OUT + (size_t)l * 65536,  256, 256);
        wtT_kernel<<<dim3(32, 8), tb32x8>>>(W1   + (size_t)l * 262144, wtf + WOFF_W1  + (size_t)l * 262144, 256, 1024);
        wtT_kernel<<<dim3(8, 32), tb32x8>>>(W2   + (size_t)l * 262144, wtf + WOFF_W2  + (size_t)l * 262144, 1024, 256);
    }

    gather_kernel<<<g_gather, tb32x8>>>(x, h);

    tcgemm_kernel<true, false, false, false><<<dim3(1, 512), 256, TCG_SMEM>>>(h, wtf + WOFF_PATCH, b_patch, nullptr, t, TOK, 256, 256);

    bp_kernel<<<dim3(8, 2), 64>>>(bias_table, headsita);

    for (int l = 0; l < 2; l++) {
        ln_kernel<<<8192, tb32x8>>>(t, ln1_g + l * 256, ln1_b + l * 256, h);
        tcgemm_kernel<false, false, false, false><<<dim3(3, 512), 256, TCG_SMEM>>>(h, wtf + WOFF_QKV + (size_t)l * 196608, nullptr, nullptr, qkvb, TOK, 768, 256);
        attn_kernel<<<dim3(8, NWIN), 64>>>(qkvb, attns, ob, l);
        tcgemm_kernel<true, false, true, false><<<dim3(1, 512), 256, TCG_SMEM>>>(ob, wtf + WOFF_OUT + (size_t)l * 65536, bout + l * 256, t, t, TOK, 256, 256);
        ln_kernel<<<8192, tb32x8>>>(t, ln2_g + l * 256, ln2_b + l * 256, h);
        tcgemm_kernel<true, true, false, true><<<dim3(4, 512), 256, TCG_SMEM>>>(h, wtf + WOFF_W1 + (size_t)l * 262144, b1 + l * 1024, nullptr, mlpb, TOK, 1024, 256);
        tcgemm_kernel<true, false, true, false><<<dim3(1, 512), 256, TCG_SMEM>>>(mlpb, wtf + WOFF_W2 + (size_t)l * 262144, b2 + l * 256, t, t, TOK, 256, 1024);
    }

    reverse_kernel<<<g_gather, tb32x8>>>(t, out);
}

// round 15
// speedup vs baseline: 1.2266x; 1.0649x over previous
#include <cuda_runtime.h>
#include <cuda_bf16.h>
#include <math.h>
#include <stdint.h>

// ---------------------------------------------------------------------------
// StandardPartitionAttention  (Swin-style window attention, DEPTH=2)
// R15: tcgen05 tf32 GEMM, 128x256 tile, 2-stage cp.async pipeline (96KB smem)
//      -> 2 CTAs/SM for cross-CTA bubble filling. Single wtT_all launch and
//      launch order arranged so ncu (-s 5 -c 1) captures the qkv GEMM.
// ---------------------------------------------------------------------------

#if defined(__CUDA_ARCH_FEAT_SM103_ALL)
#define TCG_ENABLED 1
#else
#define TCG_ENABLED 0
#endif

#define TOK 65536
#define NWIN 1024

// scratch (device globals: allocation-free)
__device__ float g_t  [TOK * 256];
__device__ float g_h  [TOK * 256];
__device__ float g_qkv[TOK * 768];
__device__ float g_o  [TOK * 256];
__device__ float g_mlp[TOK * 1024];
__device__ float g_bp [2 * 8 * 64 * 64];
__device__ float g_wtf[1638400];       // tf32-rounded, TRANSPOSED weights [N,K]

#define WOFF_PATCH 0
#define WOFF_QKV   65536
#define WOFF_OUT   458752
#define WOFF_W1    589824
#define WOFF_W2    1114112

__device__ __forceinline__ unsigned f2tf(float f)
{
    unsigned u;
    asm("cvt.rna.tf32.f32 %0, %1;" : "=r"(u) : "f"(f));
    return u;
}
__device__ __forceinline__ float rtf(float f) { return __uint_as_float(f2tf(f)); }

// ---------------------------------------------------------------------------
// ALL weight transposes in one launch: src[K,N] -> dst[N,K], tf32-rounded.
// 1600 tiles of 32x32 across 9 segments.
// ---------------------------------------------------------------------------
__global__ void wtT_all_kernel(const float* __restrict__ W_patch,
                               const float* __restrict__ Wqkv,
                               const float* __restrict__ Wout,
                               const float* __restrict__ W1,
                               const float* __restrict__ W2,
                               float* __restrict__ wtf)
{
    int t = blockIdx.x;
    const float* src; float* dst; int K, N, lt;
    if      (t < 64)   { src = W_patch;          dst = wtf + WOFF_PATCH;           K = 256;  N = 256;  lt = t; }
    else if (t < 256)  { src = Wqkv;             dst = wtf + WOFF_QKV;             K = 256;  N = 768;  lt = t - 64; }
    else if (t < 448)  { src = Wqkv + 196608;    dst = wtf + WOFF_QKV + 196608;    K = 256;  N = 768;  lt = t - 256; }
    else if (t < 512)  { src = Wout;             dst = wtf + WOFF_OUT;             K = 256;  N = 256;  lt = t - 448; }
    else if (t < 576)  { src = Wout + 65536;     dst = wtf + WOFF_OUT + 65536;     K = 256;  N = 256;  lt = t - 512; }
    else if (t < 832)  { src = W1;               dst = wtf + WOFF_W1;              K = 256;  N = 1024; lt = t - 576; }
    else if (t < 1088) { src = W1 + 262144;      dst = wtf + WOFF_W1 + 262144;     K = 256;  N = 1024; lt = t - 832; }
    else if (t < 1344) { src = W2;               dst = wtf + WOFF_W2;              K = 1024; N = 256;  lt = t - 1088; }
    else               { src = W2 + 262144;      dst = wtf + WOFF_W2 + 262144;     K = 1024; N = 256;  lt = t - 1344; }

    int ntx = N >> 5;
    int n0 = (lt % ntx) * 32, k0 = (lt / ntx) * 32;

    __shared__ float s[32][33];
    int tx = threadIdx.x, ty = threadIdx.y;
#pragma unroll
    for (int i = 0; i < 4; i++)
        s[ty + i * 8][tx] = src[(size_t)(k0 + ty + i * 8) * N + n0 + tx];
    __syncthreads();
#pragma unroll
    for (int i = 0; i < 4; i++)
        dst[(size_t)(n0 + ty + i * 8) * K + k0 + tx] = rtf(s[tx][ty + i * 8]);
}

// ---------------------------------------------------------------------------
// window partition gather:  x[B,C,H,W] -> xg[token, C]   (tf32-rounded)
// ---------------------------------------------------------------------------
__global__ void gather_kernel(const float* __restrict__ x, float* __restrict__ xg)
{
    __shared__ float s[32][33];
    int bh = blockIdx.z; int b = bh >> 7; int h = bh & 127;
    int w0 = blockIdx.x * 32, c0 = blockIdx.y * 32;
    int tx = threadIdx.x, ty = threadIdx.y;
#pragma unroll
    for (int i = 0; i < 4; i++) {
        int ch = c0 + ty + i * 8;
        s[ty + i * 8][tx] = x[(((size_t)b * 256 + ch) * 128 + h) * 128 + w0 + tx];
    }
    __syncthreads();
    int wh = h >> 3, r = h & 7;
#pragma unroll
    for (int i = 0; i < 4; i++) {
        int w = w0 + ty + i * 8;
        int row = ((b * 16 + wh) * 16 + (w >> 3)) * 64 + r * 8 + (w & 7);
        xg[(size_t)row * 256 + c0 + tx] = rtf(s[tx][ty + i * 8]);
    }
}

__global__ void reverse_kernel(const float* __restrict__ t, float* __restrict__ out)
{
    __shared__ float s[32][33];
    int bh = blockIdx.z; int b = bh >> 7; int h = bh & 127;
    int w0 = blockIdx.x * 32, d0 = blockIdx.y * 32;
    int tx = threadIdx.x, ty = threadIdx.y;
    int wh = h >> 3, r = h & 7;
#pragma unroll
    for (int i = 0; i < 4; i++) {
        int w = w0 + ty + i * 8;
        int row = ((b * 16 + wh) * 16 + (w >> 3)) * 64 + r * 8 + (w & 7);
        s[ty + i * 8][tx] = t[(size_t)row * 256 + d0 + tx];
    }
    __syncthreads();
#pragma unroll
    for (int i = 0; i < 4; i++) {
        int d = d0 + ty + i * 8;
        out[(((size_t)b * 256 + d) * 128 + h) * 128 + w0 + tx] = s[tx][ty + i * 8];
    }
}

// ---------------------------------------------------------------------------
// tcgen05 tf32 SS GEMM: C[M,N] = A[M,K] @ Bt[N,K]^T (+bias)(+relu)(+resid)(+round)
// CTA tile 128x256, K chunks of 32, 2-stage cp.async pipeline, 256 threads,
// 2 CTAs/SM. SW128 layout, SBO=64/LBO=1; k8 advance = +2 desc units.
// ---------------------------------------------------------------------------
#define TCG_STAGES 2
#define TCG_A_BYTES 16384
#define TCG_B_BYTES 32768
#define TCG_STAGE_BYTES (TCG_A_BYTES + TCG_B_BYTES)      // 48KB
#define TCG_SMEM (1024 + TCG_STAGES * TCG_STAGE_BYTES + 64)

// idesc: F32 accum(0x10) | atype TF32(2<<7) | btype TF32(2<<10) | (256/8)<<17 | (128/16)<<24
#define TCG_IDESC 0x8400910u

__device__ __forceinline__ uint32_t swz(uint32_t off) { return off ^ ((off >> 3) & 0x70); }

__device__ __forceinline__ void cp16s(uint32_t daddr, const float* src)
{
    asm volatile("cp.async.cg.shared.global [%0], [%1], 16;" :: "r"(daddr), "l"(src));
}

__device__ __forceinline__ uint64_t mk_desc(uint32_t addr)
{
    return (2ULL << 61) | (1ULL << 46) | (64ULL << 32) | (1ULL << 16)
         | ((uint64_t)(addr >> 4) & 0x3FFF);
}

template<bool HAS_BIAS, bool RELU, bool RES, bool ROUND>
__global__ void __launch_bounds__(256, 2)
tcgemm_kernel(const float* __restrict__ A, const float* __restrict__ Bt,
              const float* __restrict__ bias, const float* __restrict__ resid,
              float* __restrict__ C, int M, int N, int K)
{
#if TCG_ENABLED
    extern __shared__ char smem_raw[];
    uint32_t sbase;
    asm("{ .reg .u64 t; cvta.to.shared.u64 t, %1; cvt.u32.u64 %0, t; }"
        : "=r"(sbase) : "l"(smem_raw));
    uint32_t base1k = (sbase + 1023u) & ~1023u;
    uint32_t ctrl   = base1k + TCG_STAGES * TCG_STAGE_BYTES;   // tmem ptr, then 2 mbars

    int tid = threadIdx.x;
    int bm = blockIdx.y * 128, bn = blockIdx.x * 256;

    if (tid < 32) {
        asm volatile("tcgen05.alloc.cta_group::1.sync.aligned.shared::cta.b32 [%0], %1;"
                     :: "r"(ctrl), "r"(256u) : "memory");
        asm volatile("tcgen05.relinquish_alloc_permit.cta_group::1.sync.aligned;");
    }
    if (tid == 0) {
#pragma unroll
        for (int s = 0; s < TCG_STAGES; s++)
            asm volatile("mbarrier.init.shared.b64 [%0], %1;"
                         :: "r"(ctrl + 16 + s * 8), "r"(1u) : "memory");
    }
    __syncthreads();
    uint32_t tmem_d;
    asm volatile("ld.shared.b32 %0, [%1];" : "=r"(tmem_d) : "r"(ctrl));

    int nchunks = K >> 5;

    // A: thread t covers row t>>1, 64B half (t&1): 4 cp16.
    // B: thread t covers row t (0..255), full 128B: 8 cp16.
    int a_row = tid >> 1, a_half = (tid & 1) * 64;
    const float* Abase = A  + (size_t)(bm + a_row) * K + (tid & 1) * 16;
    const float* Bbase = Bt + (size_t)(bn + tid) * K;
    uint32_t aoff[4], boff[8];
#pragma unroll
    for (int kk = 0; kk < 4; kk++) aoff[kk] = swz((uint32_t)a_row * 128 + a_half + kk * 16);
#pragma unroll
    for (int kk = 0; kk < 8; kk++) boff[kk] = swz((uint32_t)tid * 128 + kk * 16);

    // prologue: chunks 0,1 into stages 0,1
#pragma unroll
    for (int pt = 0; pt < 2; pt++) {
        uint32_t aS = base1k + pt * TCG_STAGE_BYTES;
        uint32_t bS = aS + TCG_A_BYTES;
        const float* a0 = Abase + pt * 32;
        const float* b0 = Bbase + pt * 32;
#pragma unroll
        for (int kk = 0; kk < 4; kk++) cp16s(aS + aoff[kk], a0 + kk * 4);
#pragma unroll
        for (int kk = 0; kk < 8; kk++) cp16s(bS + boff[kk], b0 + kk * 4);
        asm volatile("cp.async.commit_group;");
    }

    for (int c = 0; c < nchunks; c++) {
        int s = c & 1;
        asm volatile("cp.async.wait_group 1;");
        asm volatile("fence.proxy.async.shared::cta;" ::: "memory");
        __syncthreads();

        if (tid == 0) {
            uint32_t aS = base1k + s * TCG_STAGE_BYTES;
            uint64_t ad = mk_desc(aS);
            uint64_t bd = mk_desc(aS + TCG_A_BYTES);
#pragma unroll
            for (int kc = 0; kc < 4; kc++) {
                uint32_t en = (c > 0 || kc > 0) ? 1u : 0u;
                uint64_t a_desc = ad + kc * 2, b_desc = bd + kc * 2;
                asm volatile(
                    "{\n\t"
                    ".reg .pred p;\n\t"
                    "setp.ne.u32 p, %5, 0;\n\t"
                    "tcgen05.mma.cta_group::1.kind::tf32 [%0], %1, %2, %3, {%4, %4, %4, %4}, p;\n\t"
                    "}"
                    :: "r"(tmem_d), "l"(a_desc), "l"(b_desc), "r"(TCG_IDESC), "r"(0u), "r"(en)
                    : "memory");
            }
            asm volatile(
                "tcgen05.commit.cta_group::1.mbarrier::arrive::one.shared::cluster.b64 [%0];"
                :: "r"(ctrl + 16 + s * 8) : "memory");
        }

        // wait chunk c's MMA before refilling its stage (2-stage: refill target = stage c&1)
        {
            uint32_t mb = ctrl + 16 + s * 8;
            uint32_t pr = (uint32_t)((c >> 1) & 1);
            asm volatile(
                "{\n\t"
                ".reg .pred P;\n\t"
                "W_%=: \n\t"
                "mbarrier.try_wait.parity.acquire.cta.shared::cta.b64 P, [%0], %1, 0x989680;\n\t"
                "@!P bra W_%=;\n\t"
                "}"
                :: "r"(mb), "r"(pr) : "memory");
        }
        if (c + 2 < nchunks) {
            uint32_t aS = base1k + s * TCG_STAGE_BYTES;
            uint32_t bS = aS + TCG_A_BYTES;
            const float* a0 = Abase + (size_t)(c + 2) * 32;
            const float* b0 = Bbase + (size_t)(c + 2) * 32;
#pragma unroll
            for (int kk = 0; kk < 4; kk++) cp16s(aS + aoff[kk], a0 + kk * 4);
#pragma unroll
            for (int kk = 0; kk < 8; kk++) cp16s(bS + boff[kk], b0 + kk * 4);
        }
        asm volatile("cp.async.commit_group;");
    }

    asm volatile("tcgen05.fence::after_thread_sync;" ::: "memory");

    // epilogue: two warp groups handle col halves; LDTM -> smem -> coalesced stores
    int warp = tid >> 5, lane = tid & 31;
    int group = warp >> 2, wid2 = warp & 3;
    float* eb = (float*)(smem_raw + (base1k - sbase)) + group * (128 * 33);
    uint32_t tcol = tmem_d + group * 128;
#pragma unroll
    for (int off = 0; off < 128; off += 32) {
        uint32_t r[32];
        asm volatile(
            "tcgen05.ld.sync.aligned.32x32b.x32.b32 "
            "{%0, %1, %2, %3, %4, %5, %6, %7, "
            " %8, %9, %10, %11, %12, %13, %14, %15, "
            " %16, %17, %18, %19, %20, %21, %22, %23, "
            " %24, %25, %26, %27, %28, %29, %30, %31}, [%32];"
            : "=r"(r[0]),  "=r"(r[1]),  "=r"(r[2]),  "=r"(r[3]),
              "=r"(r[4]),  "=r"(r[5]),  "=r"(r[6]),  "=r"(r[7]),
              "=r"(r[8]),  "=r"(r[9]),  "=r"(r[10]), "=r"(r[11]),
              "=r"(r[12]), "=r"(r[13]), "=r"(r[14]), "=r"(r[15]),
              "=r"(r[16]), "=r"(r[17]), "=r"(r[18]), "=r"(r[19]),
              "=r"(r[20]), "=r"(r[21]), "=r"(r[22]), "=r"(r[23]),
              "=r"(r[24]), "=r"(r[25]), "=r"(r[26]), "=r"(r[27]),
              "=r"(r[28]), "=r"(r[29]), "=r"(r[30]), "=r"(r[31])
            : "r"(tcol + off));
        asm volatile("tcgen05.wait::ld.sync.aligned;" ::: "memory");

        int myrow = wid2 * 32 + lane;
#pragma unroll
        for (int cc = 0; cc < 32; cc++)
            eb[myrow * 33 + cc] = __uint_as_float(r[cc]);
        __syncthreads();

#pragma unroll 4
        for (int p = 0; p < 32; p++) {
            int row = p * 4 + wid2;
            int gcol = bn + group * 128 + off + lane;
            float v = eb[row * 33 + lane];
            if (HAS_BIAS) v += bias[gcol];
            if (RELU)     v = fmaxf(v, 0.f);
            if (RES)      v += resid[(size_t)(bm + row) * N + gcol];
            if (ROUND)    v = rtf(v);
            C[(size_t)(bm + row) * N + gcol] = v;
        }
        __syncthreads();
    }

    if (tid == 0) {
#pragma unroll
        for (int s = 0; s < TCG_STAGES; s++)
            asm volatile("mbarrier.inval.shared.b64 [%0];" :: "r"(ctrl + 16 + s * 8) : "memory");
    }
    if (tid < 32) {
        asm volatile("tcgen05.dealloc.cta_group::1.sync.aligned.b32 %0, %1;"
                     :: "r"(tmem_d), "r"(256u));
    }
#else
    // -------- generic-arch fallback (correct, slow; never runs on GB300) --------
    extern __shared__ float fsm[];
    int tid = threadIdx.x;
    int bm = blockIdx.y * 128, bn = blockIdx.x * 256;
    int row = bm + (tid >> 1);
    int ch  = (tid & 1) * 128;
    float acc[128];
#pragma unroll
    for (int c = 0; c < 128; c++) acc[c] = 0.f;
    for (int k0 = 0; k0 < K; k0 += 32) {
        const float* br = Bt + (size_t)(bn + tid) * K + k0;
#pragma unroll
        for (int kk = 0; kk < 32; kk += 4)
            *(float4*)(&fsm[tid * 32 + kk]) = *(const float4*)(br + kk);
        __syncthreads();
        float a[32];
        const float* ar = A + (size_t)row * K + k0;
#pragma unroll
        for (int kk = 0; kk < 32; kk++) a[kk] = ar[kk];
        for (int c = 0; c < 128; c++) {
            float s = acc[c];
#pragma unroll
            for (int kk = 0; kk < 32; kk++) s += a[kk] * fsm[(ch + c) * 32 + kk];
            acc[c] = s;
        }
        __syncthreads();
    }
    for (int c = 0; c < 128; c++) {
        float v = acc[c];
        int gcol = bn + ch + c;
        if (HAS_BIAS) v += bias[gcol];
        if (RELU)     v = fmaxf(v, 0.f);
        if (RES)      v += resid[(size_t)row * N + gcol];
        if (ROUND)    v = rtf(v);
        C[(size_t)row * N + gcol] = v;
    }
#endif
}

// ---------------------------------------------------------------------------
// LayerNorm: one warp per row of 256   (tf32-rounded output)
// ---------------------------------------------------------------------------
__global__ void ln_kernel(const float* __restrict__ x, const float* __restrict__ g,
                          const float* __restrict__ b, float* __restrict__ y)
{
    int row  = blockIdx.x * 8 + threadIdx.y;
    int lane = threadIdx.x;
    const float* xr = x + (size_t)row * 256;
    float v[8]; float s = 0.f, s2 = 0.f;
#pragma unroll
    for (int i = 0; i < 8; i++) {
        v[i] = xr[lane + i * 32];
        s  += v[i];
        s2 += v[i] * v[i];
    }
#pragma unroll
    for (int o = 16; o; o >>= 1) {
        s  += __shfl_xor_sync(0xffffffffu, s,  o);
        s2 += __shfl_xor_sync(0xffffffffu, s2, o);
    }
    float mean = s * (1.f / 256.f);
    float var  = s2 * (1.f / 256.f) - mean * mean;
    float inv  = rsqrtf(var + 1e-5f);
#pragma unroll
    for (int i = 0; i < 8; i++) {
        int c = lane + i * 32;
        y[(size_t)row * 256 + c] = rtf((v[i] - mean) * inv * g[c] + b[c]);
    }
}

// ---------------------------------------------------------------------------
// precompute bias + 0.01 * gaussian decay per (layer, head): g_bp
// ---------------------------------------------------------------------------
__global__ void bp_kernel(const float* __restrict__ bias_table,
                          const float* __restrict__ headsita)
{
    int l = blockIdx.y, head = blockIdx.x;
    int i = threadIdx.x;
    float sita   = headsita[l * 8 + head];
    float factor = 1.0f / (2.0f * sita * sita + 1e-10f);
    int ih = i >> 3, iw = i & 7;
    for (int j = 0; j < 64; j++) {
        int jh = j >> 3, jw = j & 7;
        int dh = ih - jh, dw = iw - jw;
        float fh = (float)dh * 0.125f, fw = (float)dw * 0.125f;
        float dis = fh * fh + fw * fw;
        int rpi = (dh + 7) * 15 + (dw + 7);
        float bv = bias_table[((size_t)l * 225 + rpi) * 8 + head];
        g_bp[(((size_t)l * 8 + head) * 64 + i) * 64 + j] = bv + 0.01f * __expf(-factor * dis);
    }
}

// ---------------------------------------------------------------------------
// attention per (window, head): 64 threads, thread i owns query row i.
// ---------------------------------------------------------------------------
__global__ void __launch_bounds__(64)
attn_kernel(const float* __restrict__ qkv, float* __restrict__ attns_out,
            float* __restrict__ obuf, int layer)
{
    const float SCALE = 0.17677669529663689f;  // 32^-0.5
    int head = blockIdx.x;
    int win  = blockIdx.y;
    int i    = threadIdx.x;

    __shared__ float ks[64][32];
    __shared__ float vs[64][32];

    const float* base = qkv + (size_t)win * 64 * 768 + head * 32;
    float q[32];
#pragma unroll
    for (int d = 0; d < 32; d++) q[d]      = base[(size_t)i * 768 + d];
#pragma unroll
    for (int d = 0; d < 32; d++) ks[i][d]  = base[(size_t)i * 768 + 256 + d];
#pragma unroll
    for (int d = 0; d < 32; d++) vs[i][d]  = base[(size_t)i * 768 + 512 + d];
    __syncthreads();

    float dots[64];
#pragma unroll 4
    for (int j = 0; j < 64; j++) {
        float s = 0.f;
#pragma unroll
        for (int d = 0; d < 32; d++) s += q[d] * ks[j][d];
        dots[j] = s * SCALE;
    }

    float m0 = -1e30f;
#pragma unroll
    for (int j = 0; j < 64; j++) m0 = fmaxf(m0, dots[j]);
    float sum0 = 0.f;
#pragma unroll
    for (int j = 0; j < 64; j++) sum0 += __expf(dots[j] - m0);
    float inv0 = 1.f / sum0;
    float* arow = attns_out + (((size_t)layer * NWIN + win) * 8 + head) * 4096 + (size_t)i * 64;
#pragma unroll
    for (int j = 0; j < 64; j++) arow[j] = __expf(dots[j] - m0) * inv0;

    const float* bp = g_bp + (((size_t)layer * 8 + head) * 64 + i) * 64;
#pragma unroll
    for (int j = 0; j < 64; j++) dots[j] += bp[j];
    float m1 = -1e30f;
#pragma unroll
    for (int j = 0; j < 64; j++) m1 = fmaxf(m1, dots[j]);
    float sum1 = 0.f;
#pragma unroll
    for (int j = 0; j < 64; j++) { dots[j] = __expf(dots[j] - m1); sum1 += dots[j]; }
    float inv1 = 1.f / sum1;

    float acc[32];
#pragma unroll
    for (int d = 0; d < 32; d++) acc[d] = 0.f;
#pragma unroll 4
    for (int j = 0; j < 64; j++) {
        float a = dots[j] * inv1;
#pragma unroll
        for (int d = 0; d < 32; d++) acc[d] += a * vs[j][d];
    }
    float* orow = obuf + (size_t)(win * 64 + i) * 256 + head * 32;
#pragma unroll
    for (int d = 0; d < 32; d++) orow[d] = rtf(acc[d]);
}

// ---------------------------------------------------------------------------
extern "C" void kernel_launch(void* const* d_in, const int* in_sizes, int n_in,
                              void* d_out, int out_size)
{
    const float* x          = (const float*)d_in[0];
    const float* W_patch    = (const float*)d_in[1];
    const float* b_patch    = (const float*)d_in[2];
    const float* ln1_g      = (const float*)d_in[3];
    const float* ln1_b      = (const float*)d_in[4];
    const float* Wqkv       = (const float*)d_in[5];
    const float* headsita   = (const float*)d_in[6];
    const float* bias_table = (const float*)d_in[7];
    const float* Wout       = (const float*)d_in[8];
    const float* bout       = (const float*)d_in[9];
    const float* ln2_g      = (const float*)d_in[10];
    const float* ln2_b      = (const float*)d_in[11];
    const float* W1         = (const float*)d_in[12];
    const float* b1         = (const float*)d_in[13];
    const float* W2         = (const float*)d_in[14];
    const float* b2         = (const float*)d_in[15];

    float* out   = (float*)d_out;
    float* attns = out + (size_t)16777216;

    float *t, *h, *qkvb, *ob, *mlpb, *wtf;
    cudaGetSymbolAddress((void**)&t,    g_t);
    cudaGetSymbolAddress((void**)&h,    g_h);
    cudaGetSymbolAddress((void**)&qkvb, g_qkv);
    cudaGetSymbolAddress((void**)&ob,   g_o);
    cudaGetSymbolAddress((void**)&mlpb, g_mlp);
    cudaGetSymbolAddress((void**)&wtf,  g_wtf);

    static bool attr_done = false;
    if (!attr_done) {
        cudaFuncSetAttribute(tcgemm_kernel<true,  false, false, false>, cudaFuncAttributeMaxDynamicSharedMemorySize, TCG_SMEM);
        cudaFuncSetAttribute(tcgemm_kernel<false, false, false, false>, cudaFuncAttributeMaxDynamicSharedMemorySize, TCG_SMEM);
        cudaFuncSetAttribute(tcgemm_kernel<true,  false, true,  false>, cudaFuncAttributeMaxDynamicSharedMemorySize, TCG_SMEM);
        cudaFuncSetAttribute(tcgemm_kernel<true,  true,  false, true >, cudaFuncAttributeMaxDynamicSharedMemorySize, TCG_SMEM);
        attr_done = true;
    }

    dim3 tb32x8(32, 8);
    dim3 g_gather(4, 8, 512);

    // launch order arranged so launch #6 (ncu -s 5 -c 1) = qkv tcgemm (layer 0)
    wtT_all_kernel<<<1600, tb32x8>>>(W_patch, Wqkv, Wout, W1, W2, wtf);                                       // 1
    gather_kernel<<<g_gather, tb32x8>>>(x, h);                                                                 // 2
    tcgemm_kernel<true, false, false, false><<<dim3(1, 512), 256, TCG_SMEM>>>(h, wtf + WOFF_PATCH, b_patch, nullptr, t, TOK, 256, 256); // 3
    bp_kernel<<<dim3(8, 2), 64>>>(bias_table, headsita);                                                       // 4

    for (int l = 0; l < 2; l++) {
        ln_kernel<<<8192, tb32x8>>>(t, ln1_g + l * 256, ln1_b + l * 256, h);                                   // 5
        tcgemm_kernel<false, false, false, false><<<dim3(3, 512), 256, TCG_SMEM>>>(h, wtf + WOFF_QKV + (size_t)l * 196608, nullptr, nullptr, qkvb, TOK, 768, 256); // 6 <- profiled
        attn_kernel<<<dim3(8, NWIN), 64>>>(qkvb, attns, ob, l);
        tcgemm_kernel<true, false, true, false><<<dim3(1, 512), 256, TCG_SMEM>>>(ob, wtf + WOFF_OUT + (size_t)l * 65536, bout + l * 256, t, t, TOK, 256, 256);
        ln_kernel<<<8192, tb32x8>>>(t, ln2_g + l * 256, ln2_b + l * 256, h);
        tcgemm_kernel<true, true, false, true><<<dim3(4, 512), 256, TCG_SMEM>>>(h, wtf + WOFF_W1 + (size_t)l * 262144, b1 + l * 1024, nullptr, mlpb, TOK, 1024, 256);
        tcgemm_kernel<true, false, true, false><<<dim3(1, 512), 256, TCG_SMEM>>>(mlpb, wtf + WOFF_W2 + (size_t)l * 262144, b2 + l * 256, t, t, TOK, 256, 1024);
    }

    reverse_kernel<<<g_gather, tb32x8>>>(t, out);
}

// round 16
// speedup vs baseline: 1.2277x; 1.0009x over previous
#include <cuda_runtime.h>
#include <cuda_bf16.h>
#include <math.h>
#include <stdint.h>

// ---------------------------------------------------------------------------
// StandardPartitionAttention  (Swin-style window attention, DEPTH=2)
// R15: tcgen05 tf32 GEMM, 128x256 tile, 2-stage cp.async pipeline (96KB smem)
//      -> 2 CTAs/SM for cross-CTA bubble filling. Single wtT_all launch and
//      launch order arranged so ncu (-s 5 -c 1) captures the qkv GEMM.
// ---------------------------------------------------------------------------

#if defined(__CUDA_ARCH_FEAT_SM103_ALL)
#define TCG_ENABLED 1
#else
#define TCG_ENABLED 0
#endif

#define TOK 65536
#define NWIN 1024

// scratch (device globals: allocation-free)
__device__ float g_t  [TOK * 256];
__device__ float g_h  [TOK * 256];
__device__ float g_qkv[TOK * 768];
__device__ float g_o  [TOK * 256];
__device__ float g_mlp[TOK * 1024];
__device__ float g_bp [2 * 8 * 64 * 64];
__device__ float g_wtf[1638400];       // tf32-rounded, TRANSPOSED weights [N,K]

#define WOFF_PATCH 0
#define WOFF_QKV   65536
#define WOFF_OUT   458752
#define WOFF_W1    589824
#define WOFF_W2    1114112

__device__ __forceinline__ unsigned f2tf(float f)
{
    unsigned u;
    asm("cvt.rna.tf32.f32 %0, %1;" : "=r"(u) : "f"(f));
    return u;
}
__device__ __forceinline__ float rtf(float f) { return __uint_as_float(f2tf(f)); }

// ---------------------------------------------------------------------------
// ALL weight transposes in one launch: src[K,N] -> dst[N,K], tf32-rounded.
// 1600 tiles of 32x32 across 9 segments.
// ---------------------------------------------------------------------------
__global__ void wtT_all_kernel(const float* __restrict__ W_patch,
                               const float* __restrict__ Wqkv,
                               const float* __restrict__ Wout,
                               const float* __restrict__ W1,
                               const float* __restrict__ W2,
                               float* __restrict__ wtf)
{
    int t = blockIdx.x;
    const float* src; float* dst; int K, N, lt;
    if      (t < 64)   { src = W_patch;          dst = wtf + WOFF_PATCH;           K = 256;  N = 256;  lt = t; }
    else if (t < 256)  { src = Wqkv;             dst = wtf + WOFF_QKV;             K = 256;  N = 768;  lt = t - 64; }
    else if (t < 448)  { src = Wqkv + 196608;    dst = wtf + WOFF_QKV + 196608;    K = 256;  N = 768;  lt = t - 256; }
    else if (t < 512)  { src = Wout;             dst = wtf + WOFF_OUT;             K = 256;  N = 256;  lt = t - 448; }
    else if (t < 576)  { src = Wout + 65536;     dst = wtf + WOFF_OUT + 65536;     K = 256;  N = 256;  lt = t - 512; }
    else if (t < 832)  { src = W1;               dst = wtf + WOFF_W1;              K = 256;  N = 1024; lt = t - 576; }
    else if (t < 1088) { src = W1 + 262144;      dst = wtf + WOFF_W1 + 262144;     K = 256;  N = 1024; lt = t - 832; }
    else if (t < 1344) { src = W2;               dst = wtf + WOFF_W2;              K = 1024; N = 256;  lt = t - 1088; }
    else               { src = W2 + 262144;      dst = wtf + WOFF_W2 + 262144;     K = 1024; N = 256;  lt = t - 1344; }

    int ntx = N >> 5;
    int n0 = (lt % ntx) * 32, k0 = (lt / ntx) * 32;

    __shared__ float s[32][33];
    int tx = threadIdx.x, ty = threadIdx.y;
#pragma unroll
    for (int i = 0; i < 4; i++)
        s[ty + i * 8][tx] = src[(size_t)(k0 + ty + i * 8) * N + n0 + tx];
    __syncthreads();
#pragma unroll
    for (int i = 0; i < 4; i++)
        dst[(size_t)(n0 + ty + i * 8) * K + k0 + tx] = rtf(s[tx][ty + i * 8]);
}

// ---------------------------------------------------------------------------
// window partition gather:  x[B,C,H,W] -> xg[token, C]   (tf32-rounded)
// ---------------------------------------------------------------------------
__global__ void gather_kernel(const float* __restrict__ x, float* __restrict__ xg)
{
    __shared__ float s[32][33];
    int bh = blockIdx.z; int b = bh >> 7; int h = bh & 127;
    int w0 = blockIdx.x * 32, c0 = blockIdx.y * 32;
    int tx = threadIdx.x, ty = threadIdx.y;
#pragma unroll
    for (int i = 0; i < 4; i++) {
        int ch = c0 + ty + i * 8;
        s[ty + i * 8][tx] = x[(((size_t)b * 256 + ch) * 128 + h) * 128 + w0 + tx];
    }
    __syncthreads();
    int wh = h >> 3, r = h & 7;
#pragma unroll
    for (int i = 0; i < 4; i++) {
        int w = w0 + ty + i * 8;
        int row = ((b * 16 + wh) * 16 + (w >> 3)) * 64 + r * 8 + (w & 7);
        xg[(size_t)row * 256 + c0 + tx] = rtf(s[tx][ty + i * 8]);
    }
}

__global__ void reverse_kernel(const float* __restrict__ t, float* __restrict__ out)
{
    __shared__ float s[32][33];
    int bh = blockIdx.z; int b = bh >> 7; int h = bh & 127;
    int w0 = blockIdx.x * 32, d0 = blockIdx.y * 32;
    int tx = threadIdx.x, ty = threadIdx.y;
    int wh = h >> 3, r = h & 7;
#pragma unroll
    for (int i = 0; i < 4; i++) {
        int w = w0 + ty + i * 8;
        int row = ((b * 16 + wh) * 16 + (w >> 3)) * 64 + r * 8 + (w & 7);
        s[ty + i * 8][tx] = t[(size_t)row * 256 + d0 + tx];
    }
    __syncthreads();
#pragma unroll
    for (int i = 0; i < 4; i++) {
        int d = d0 + ty + i * 8;
        out[(((size_t)b * 256 + d) * 128 + h) * 128 + w0 + tx] = s[tx][ty + i * 8];
    }
}

// ---------------------------------------------------------------------------
// tcgen05 tf32 SS GEMM: C[M,N] = A[M,K] @ Bt[N,K]^T (+bias)(+relu)(+resid)(+round)
// CTA tile 128x256, K chunks of 32, 2-stage cp.async pipeline, 256 threads,
// 2 CTAs/SM. SW128 layout, SBO=64/LBO=1; k8 advance = +2 desc units.
// ---------------------------------------------------------------------------
#define TCG_STAGES 2
#define TCG_A_BYTES 16384
#define TCG_B_BYTES 32768
#define TCG_STAGE_BYTES (TCG_A_BYTES + TCG_B_BYTES)      // 48KB
#define TCG_SMEM (1024 + TCG_STAGES * TCG_STAGE_BYTES + 64)

// idesc: F32 accum(0x10) | atype TF32(2<<7) | btype TF32(2<<10) | (256/8)<<17 | (128/16)<<24
#define TCG_IDESC 0x8400910u

__device__ __forceinline__ uint32_t swz(uint32_t off) { return off ^ ((off >> 3) & 0x70); }

__device__ __forceinline__ void cp16s(uint32_t daddr, const float* src)
{
    asm volatile("cp.async.cg.shared.global [%0], [%1], 16;" :: "r"(daddr), "l"(src));
}

__device__ __forceinline__ uint64_t mk_desc(uint32_t addr)
{
    return (2ULL << 61) | (1ULL << 46) | (64ULL << 32) | (1ULL << 16)
         | ((uint64_t)(addr >> 4) & 0x3FFF);
}

template<bool HAS_BIAS, bool RELU, bool RES, bool ROUND>
__global__ void __launch_bounds__(256, 2)
tcgemm_kernel(const float* __restrict__ A, const float* __restrict__ Bt,
              const float* __restrict__ bias, const float* __restrict__ resid,
              float* __restrict__ C, int M, int N, int K)
{
#if TCG_ENABLED
    extern __shared__ char smem_raw[];
    uint32_t sbase;
    asm("{ .reg .u64 t; cvta.to.shared.u64 t, %1; cvt.u32.u64 %0, t; }"
        : "=r"(sbase) : "l"(smem_raw));
    uint32_t base1k = (sbase + 1023u) & ~1023u;
    uint32_t ctrl   = base1k + TCG_STAGES * TCG_STAGE_BYTES;   // tmem ptr, then 2 mbars

    int tid = threadIdx.x;
    int bm = blockIdx.y * 128, bn = blockIdx.x * 256;

    if (tid < 32) {
        asm volatile("tcgen05.alloc.cta_group::1.sync.aligned.shared::cta.b32 [%0], %1;"
                     :: "r"(ctrl), "r"(256u) : "memory");
        asm volatile("tcgen05.relinquish_alloc_permit.cta_group::1.sync.aligned;");
    }
    if (tid == 0) {
#pragma unroll
        for (int s = 0; s < TCG_STAGES; s++)
            asm volatile("mbarrier.init.shared.b64 [%0], %1;"
                         :: "r"(ctrl + 16 + s * 8), "r"(1u) : "memory");
    }
    __syncthreads();
    uint32_t tmem_d;
    asm volatile("ld.shared.b32 %0, [%1];" : "=r"(tmem_d) : "r"(ctrl));

    int nchunks = K >> 5;

    // A: thread t covers row t>>1, 64B half (t&1): 4 cp16.
    // B: thread t covers row t (0..255), full 128B: 8 cp16.
    int a_row = tid >> 1, a_half = (tid & 1) * 64;
    const float* Abase = A  + (size_t)(bm + a_row) * K + (tid & 1) * 16;
    const float* Bbase = Bt + (size_t)(bn + tid) * K;
    uint32_t aoff[4], boff[8];
#pragma unroll
    for (int kk = 0; kk < 4; kk++) aoff[kk] = swz((uint32_t)a_row * 128 + a_half + kk * 16);
#pragma unroll
    for (int kk = 0; kk < 8; kk++) boff[kk] = swz((uint32_t)tid * 128 + kk * 16);

    // prologue: chunks 0,1 into stages 0,1
#pragma unroll
    for (int pt = 0; pt < 2; pt++) {
        uint32_t aS = base1k + pt * TCG_STAGE_BYTES;
        uint32_t bS = aS + TCG_A_BYTES;
        const float* a0 = Abase + pt * 32;
        const float* b0 = Bbase + pt * 32;
#pragma unroll
        for (int kk = 0; kk < 4; kk++) cp16s(aS + aoff[kk], a0 + kk * 4);
#pragma unroll
        for (int kk = 0; kk < 8; kk++) cp16s(bS + boff[kk], b0 + kk * 4);
        asm volatile("cp.async.commit_group;");
    }

    for (int c = 0; c < nchunks; c++) {
        int s = c & 1;
        asm volatile("cp.async.wait_group 1;");
        asm volatile("fence.proxy.async.shared::cta;" ::: "memory");
        __syncthreads();

        if (tid == 0) {
            uint32_t aS = base1k + s * TCG_STAGE_BYTES;
            uint64_t ad = mk_desc(aS);
            uint64_t bd = mk_desc(aS + TCG_A_BYTES);
#pragma unroll
            for (int kc = 0; kc < 4; kc++) {
                uint32_t en = (c > 0 || kc > 0) ? 1u : 0u;
                uint64_t a_desc = ad + kc * 2, b_desc = bd + kc * 2;
                asm volatile(
                    "{\n\t"
                    ".reg .pred p;\n\t"
                    "setp.ne.u32 p, %5, 0;\n\t"
                    "tcgen05.mma.cta_group::1.kind::tf32 [%0], %1, %2, %3, {%4, %4, %4, %4}, p;\n\t"
                    "}"
                    :: "r"(tmem_d), "l"(a_desc), "l"(b_desc), "r"(TCG_IDESC), "r"(0u), "r"(en)
                    : "memory");
            }
            asm volatile(
                "tcgen05.commit.cta_group::1.mbarrier::arrive::one.shared::cluster.b64 [%0];"
                :: "r"(ctrl + 16 + s * 8) : "memory");
        }

        // wait chunk c's MMA before refilling its stage (2-stage: refill target = stage c&1)
        {
            uint32_t mb = ctrl + 16 + s * 8;
            uint32_t pr = (uint32_t)((c >> 1) & 1);
            asm volatile(
                "{\n\t"
                ".reg .pred P;\n\t"
                "W_%=: \n\t"
                "mbarrier.try_wait.parity.acquire.cta.shared::cta.b64 P, [%0], %1, 0x989680;\n\t"
                "@!P bra W_%=;\n\t"
                "}"
                :: "r"(mb), "r"(pr) : "memory");
        }
        if (c + 2 < nchunks) {
            uint32_t aS = base1k + s * TCG_STAGE_BYTES;
            uint32_t bS = aS + TCG_A_BYTES;
            const float* a0 = Abase + (size_t)(c + 2) * 32;
            const float* b0 = Bbase + (size_t)(c + 2) * 32;
#pragma unroll
            for (int kk = 0; kk < 4; kk++) cp16s(aS + aoff[kk], a0 + kk * 4);
#pragma unroll
            for (int kk = 0; kk < 8; kk++) cp16s(bS + boff[kk], b0 + kk * 4);
        }
        asm volatile("cp.async.commit_group;");
    }

    asm volatile("tcgen05.fence::after_thread_sync;" ::: "memory");

    // epilogue: two warp groups handle col halves; LDTM -> smem -> coalesced stores
    int warp = tid >> 5, lane = tid & 31;
    int group = warp >> 2, wid2 = warp & 3;
    float* eb = (float*)(smem_raw + (base1k - sbase)) + group * (128 * 33);
    uint32_t tcol = tmem_d + group * 128;
#pragma unroll
    for (int off = 0; off < 128; off += 32) {
        uint32_t r[32];
        asm volatile(
            "tcgen05.ld.sync.aligned.32x32b.x32.b32 "
            "{%0, %1, %2, %3, %4, %5, %6, %7, "
            " %8, %9, %10, %11, %12, %13, %14, %15, "
            " %16, %17, %18, %19, %20, %21, %22, %23, "
            " %24, %25, %26, %27, %28, %29, %30, %31}, [%32];"
            : "=r"(r[0]),  "=r"(r[1]),  "=r"(r[2]),  "=r"(r[3]),
              "=r"(r[4]),  "=r"(r[5]),  "=r"(r[6]),  "=r"(r[7]),
              "=r"(r[8]),  "=r"(r[9]),  "=r"(r[10]), "=r"(r[11]),
              "=r"(r[12]), "=r"(r[13]), "=r"(r[14]), "=r"(r[15]),
              "=r"(r[16]), "=r"(r[17]), "=r"(r[18]), "=r"(r[19]),
              "=r"(r[20]), "=r"(r[21]), "=r"(r[22]), "=r"(r[23]),
              "=r"(r[24]), "=r"(r[25]), "=r"(r[26]), "=r"(r[27]),
              "=r"(r[28]), "=r"(r[29]), "=r"(r[30]), "=r"(r[31])
            : "r"(tcol + off));
        asm volatile("tcgen05.wait::ld.sync.aligned;" ::: "memory");

        int myrow = wid2 * 32 + lane;
#pragma unroll
        for (int cc = 0; cc < 32; cc++)
            eb[myrow * 33 + cc] = __uint_as_float(r[cc]);
        __syncthreads();

#pragma unroll 4
        for (int p = 0; p < 32; p++) {
            int row = p * 4 + wid2;
            int gcol = bn + group * 128 + off + lane;
            float v = eb[row * 33 + lane];
            if (HAS_BIAS) v += bias[gcol];
            if (RELU)     v = fmaxf(v, 0.f);
            if (RES)      v += resid[(size_t)(bm + row) * N + gcol];
            if (ROUND)    v = rtf(v);
            C[(size_t)(bm + row) * N + gcol] = v;
        }
        __syncthreads();
    }

    if (tid == 0) {
#pragma unroll
        for (int s = 0; s < TCG_STAGES; s++)
            asm volatile("mbarrier.inval.shared.b64 [%0];" :: "r"(ctrl + 16 + s * 8) : "memory");
    }
    if (tid < 32) {
        asm volatile("tcgen05.dealloc.cta_group::1.sync.aligned.b32 %0, %1;"
                     :: "r"(tmem_d), "r"(256u));
    }
#else
    // -------- generic-arch fallback (correct, slow; never runs on GB300) --------
    extern __shared__ float fsm[];
    int tid = threadIdx.x;
    int bm = blockIdx.y * 128, bn = blockIdx.x * 256;
    int row = bm + (tid >> 1);
    int ch  = (tid & 1) * 128;
    float acc[128];
#pragma unroll
    for (int c = 0; c < 128; c++) acc[c] = 0.f;
    for (int k0 = 0; k0 < K; k0 += 32) {
        const float* br = Bt + (size_t)(bn + tid) * K + k0;
#pragma unroll
        for (int kk = 0; kk < 32; kk += 4)
            *(float4*)(&fsm[tid * 32 + kk]) = *(const float4*)(br + kk);
        __syncthreads();
        float a[32];
        const float* ar = A + (size_t)row * K + k0;
#pragma unroll
        for (int kk = 0; kk < 32; kk++) a[kk] = ar[kk];
        for (int c = 0; c < 128; c++) {
            float s = acc[c];
#pragma unroll
            for (int kk = 0; kk < 32; kk++) s += a[kk] * fsm[(ch + c) * 32 + kk];
            acc[c] = s;
        }
        __syncthreads();
    }
    for (int c = 0; c < 128; c++) {
        float v = acc[c];
        int gcol = bn + ch + c;
        if (HAS_BIAS) v += bias[gcol];
        if (RELU)     v = fmaxf(v, 0.f);
        if (RES)      v += resid[(size_t)row * N + gcol];
        if (ROUND)    v = rtf(v);
        C[(size_t)row * N + gcol] = v;
    }
#endif
}

// ---------------------------------------------------------------------------
// LayerNorm: one warp per row of 256   (tf32-rounded output)
// ---------------------------------------------------------------------------
__global__ void ln_kernel(const float* __restrict__ x, const float* __restrict__ g,
                          const float* __restrict__ b, float* __restrict__ y)
{
    int row  = blockIdx.x * 8 + threadIdx.y;
    int lane = threadIdx.x;
    const float* xr = x + (size_t)row * 256;
    float v[8]; float s = 0.f, s2 = 0.f;
#pragma unroll
    for (int i = 0; i < 8; i++) {
        v[i] = xr[lane + i * 32];
        s  += v[i];
        s2 += v[i] * v[i];
    }
#pragma unroll
    for (int o = 16; o; o >>= 1) {
        s  += __shfl_xor_sync(0xffffffffu, s,  o);
        s2 += __shfl_xor_sync(0xffffffffu, s2, o);
    }
    float mean = s * (1.f / 256.f);
    float var  = s2 * (1.f / 256.f) - mean * mean;
    float inv  = rsqrtf(var + 1e-5f);
#pragma unroll
    for (int i = 0; i < 8; i++) {
        int c = lane + i * 32;
        y[(size_t)row * 256 + c] = rtf((v[i] - mean) * inv * g[c] + b[c]);
    }
}

// ---------------------------------------------------------------------------
// precompute bias + 0.01 * gaussian decay per (layer, head): g_bp
// ---------------------------------------------------------------------------
__global__ void bp_kernel(const float* __restrict__ bias_table,
                          const float* __restrict__ headsita)
{
    int l = blockIdx.y, head = blockIdx.x;
    int i = threadIdx.x;
    float sita   = headsita[l * 8 + head];
    float factor = 1.0f / (2.0f * sita * sita + 1e-10f);
    int ih = i >> 3, iw = i & 7;
    for (int j = 0; j < 64; j++) {
        int jh = j >> 3, jw = j & 7;
        int dh = ih - jh, dw = iw - jw;
        float fh = (float)dh * 0.125f, fw = (float)dw * 0.125f;
        float dis = fh * fh + fw * fw;
        int rpi = (dh + 7) * 15 + (dw + 7);
        float bv = bias_table[((size_t)l * 225 + rpi) * 8 + head];
        g_bp[(((size_t)l * 8 + head) * 64 + i) * 64 + j] = bv + 0.01f * __expf(-factor * dis);
    }
}

// ---------------------------------------------------------------------------
// attention per (window, head): 64 threads, thread i owns query row i.
// ---------------------------------------------------------------------------
__global__ void __launch_bounds__(64)
attn_kernel(const float* __restrict__ qkv, float* __restrict__ attns_out,
            float* __restrict__ obuf, int layer)
{
    const float SCALE = 0.17677669529663689f;  // 32^-0.5
    int head = blockIdx.x;
    int win  = blockIdx.y;
    int i    = threadIdx.x;

    __shared__ float ks[64][32];
    __shared__ float vs[64][32];

    const float* base = qkv + (size_t)win * 64 * 768 + head * 32;
    float q[32];
#pragma unroll
    for (int d = 0; d < 32; d++) q[d]      = base[(size_t)i * 768 + d];
#pragma unroll
    for (int d = 0; d < 32; d++) ks[i][d]  = base[(size_t)i * 768 + 256 + d];
#pragma unroll
    for (int d = 0; d < 32; d++) vs[i][d]  = base[(size_t)i * 768 + 512 + d];
    __syncthreads();

    float dots[64];
#pragma unroll 4
    for (int j = 0; j < 64; j++) {
        float s = 0.f;
#pragma unroll
        for (int d = 0; d < 32; d++) s += q[d] * ks[j][d];
        dots[j] = s * SCALE;
    }

    float m0 = -1e30f;
#pragma unroll
    for (int j = 0; j < 64; j++) m0 = fmaxf(m0, dots[j]);
    float sum0 = 0.f;
#pragma unroll
    for (int j = 0; j < 64; j++) sum0 += __expf(dots[j] - m0);
    float inv0 = 1.f / sum0;
    float* arow = attns_out + (((size_t)layer * NWIN + win) * 8 + head) * 4096 + (size_t)i * 64;
#pragma unroll
    for (int j = 0; j < 64; j++) arow[j] = __expf(dots[j] - m0) * inv0;

    const float* bp = g_bp + (((size_t)layer * 8 + head) * 64 + i) * 64;
#pragma unroll
    for (int j = 0; j < 64; j++) dots[j] += bp[j];
    float m1 = -1e30f;
#pragma unroll
    for (int j = 0; j < 64; j++) m1 = fmaxf(m1, dots[j]);
    float sum1 = 0.f;
#pragma unroll
    for (int j = 0; j < 64; j++) { dots[j] = __expf(dots[j] - m1); sum1 += dots[j]; }
    float inv1 = 1.f / sum1;

    float acc[32];
#pragma unroll
    for (int d = 0; d < 32; d++) acc[d] = 0.f;
#pragma unroll 4
    for (int j = 0; j < 64; j++) {
        float a = dots[j] * inv1;
#pragma unroll
        for (int d = 0; d < 32; d++) acc[d] += a * vs[j][d];
    }
    float* orow = obuf + (size_t)(win * 64 + i) * 256 + head * 32;
#pragma unroll
    for (int d = 0; d < 32; d++) orow[d] = rtf(acc[d]);
}

// ---------------------------------------------------------------------------
extern "C" void kernel_launch(void* const* d_in, const int* in_sizes, int n_in,
                              void* d_out, int out_size)
{
    const float* x          = (const float*)d_in[0];
    const float* W_patch    = (const float*)d_in[1];
    const float* b_patch    = (const float*)d_in[2];
    const float* ln1_g      = (const float*)d_in[3];
    const float* ln1_b      = (const float*)d_in[4];
    const float* Wqkv       = (const float*)d_in[5];
    const float* headsita   = (const float*)d_in[6];
    const float* bias_table = (const float*)d_in[7];
    const float* Wout       = (const float*)d_in[8];
    const float* bout       = (const float*)d_in[9];
    const float* ln2_g      = (const float*)d_in[10];
    const float* ln2_b      = (const float*)d_in[11];
    const float* W1         = (const float*)d_in[12];
    const float* b1         = (const float*)d_in[13];
    const float* W2         = (const float*)d_in[14];
    const float* b2         = (const float*)d_in[15];

    float* out   = (float*)d_out;
    float* attns = out + (size_t)16777216;

    float *t, *h, *qkvb, *ob, *mlpb, *wtf;
    cudaGetSymbolAddress((void**)&t,    g_t);
    cudaGetSymbolAddress((void**)&h,    g_h);
    cudaGetSymbolAddress((void**)&qkvb, g_qkv);
    cudaGetSymbolAddress((void**)&ob,   g_o);
    cudaGetSymbolAddress((void**)&mlpb, g_mlp);
    cudaGetSymbolAddress((void**)&wtf,  g_wtf);

    static bool attr_done = false;
    if (!attr_done) {
        cudaFuncSetAttribute(tcgemm_kernel<true,  false, false, false>, cudaFuncAttributeMaxDynamicSharedMemorySize, TCG_SMEM);
        cudaFuncSetAttribute(tcgemm_kernel<false, false, false, false>, cudaFuncAttributeMaxDynamicSharedMemorySize, TCG_SMEM);
        cudaFuncSetAttribute(tcgemm_kernel<true,  false, true,  false>, cudaFuncAttributeMaxDynamicSharedMemorySize, TCG_SMEM);
        cudaFuncSetAttribute(tcgemm_kernel<true,  true,  false, true >, cudaFuncAttributeMaxDynamicSharedMemorySize, TCG_SMEM);
        attr_done = true;
    }

    dim3 tb32x8(32, 8);
    dim3 g_gather(4, 8, 512);

    // launch order arranged so launch #6 (ncu -s 5 -c 1) = qkv tcgemm (layer 0)
    wtT_all_kernel<<<1600, tb32x8>>>(W_patch, Wqkv, Wout, W1, W2, wtf);                                       // 1
    gather_kernel<<<g_gather, tb32x8>>>(x, h);                                                                 // 2
    tcgemm_kernel<true, false, false, false><<<dim3(1, 512), 256, TCG_SMEM>>>(h, wtf + WOFF_PATCH, b_patch, nullptr, t, TOK, 256, 256); // 3
    bp_kernel<<<dim3(8, 2), 64>>>(bias_table, headsita);                                                       // 4

    for (int l = 0; l < 2; l++) {
        ln_kernel<<<8192, tb32x8>>>(t, ln1_g + l * 256, ln1_b + l * 256, h);                                   // 5
        tcgemm_kernel<false, false, false, false><<<dim3(3, 512), 256, TCG_SMEM>>>(h, wtf + WOFF_QKV + (size_t)l * 196608, nullptr, nullptr, qkvb, TOK, 768, 256); // 6 <- profiled
        attn_kernel<<<dim3(8, NWIN), 64>>>(qkvb, attns, ob, l);
        tcgemm_kernel<true, false, true, false><<<dim3(1, 512), 256, TCG_SMEM>>>(ob, wtf + WOFF_OUT + (size_t)l * 65536, bout + l * 256, t, t, TOK, 256, 256);
        ln_kernel<<<8192, tb32x8>>>(t, ln2_g + l * 256, ln2_b + l * 256, h);
        tcgemm_kernel<true, true, false, true><<<dim3(4, 512), 256, TCG_SMEM>>>(h, wtf + WOFF_W1 + (size_t)l * 262144, b1 + l * 1024, nullptr, mlpb, TOK, 1024, 256);
        tcgemm_kernel<true, false, true, false><<<dim3(1, 512), 256, TCG_SMEM>>>(mlpb, wtf + WOFF_W2 + (size_t)l * 262144, b2 + l * 256, t, t, TOK, 256, 1024);
    }

    reverse_kernel<<<g_gather, tb32x8>>>(t, out);
}